// round 10
// baseline (speedup 1.0000x reference)
#include <cuda_runtime.h>
#include <cuda_bf16.h>
#include <math.h>
#include <stdint.h>

// Problem constants
#define SS   4096
#define BB   16
#define CC   512
#define TMAX 512

// ---------------- device scratch (static; no cudaMalloc) ----------------------------
__device__ float g_sig  [BB * SS];          // raw sigmoid
__device__ float g_alpha[BB * SS];          // scaled alpha
__device__ float g_csum [BB * SS];
__device__ int   g_f    [BB * SS];
__device__ __align__(16) __nv_bfloat16 g_Ah[8192 * 512];
__device__ __align__(16) __nv_bfloat16 g_Al[8192 * 512];
__device__ __align__(16) __nv_bfloat16 g_Bh[512 * 512];
__device__ __align__(16) __nv_bfloat16 g_Bl[512 * 512];

__constant__ int c_off[13] = {0,4096,6144,7168,7680,7936,8064,8128,8160,8176,8184,8188,8190};

// ---------------- Phase 1a: fp64 sigmoid spread over the whole chip -----------------
__global__ __launch_bounds__(256)
void sigmoid_kernel(const float* __restrict__ x, const unsigned char* __restrict__ mask) {
    int i = blockIdx.x * 256 + threadIdx.x;    // i = b*SS + s
    int b = i >> 12;
    int s = i & (SS - 1);
    float a = mask[i] ? -10000.0f : x[(size_t)s * (BB*CC) + b * CC + (CC - 1)];
    double sg = 1.0 / (1.0 + exp(-(double)a));
    g_sig[i] = (float)sg;
}

// ---------------- Phase 1b: fp32 reduce + exact JAX-tree cumsum + fire indices ------
__device__ __forceinline__ void downsweep(float* sb, int tid) {
    for (int l = 1; l <= 12; l++) {
        int sz = SS >> l;
        int o  = c_off[l], oi = c_off[l-1];
        for (int i = tid; i < sz; i += 512)
            sb[o + i] = sb[oi + 2*i] + sb[oi + 2*i + 1];
        __syncthreads();
    }
}
__device__ __forceinline__ void upsweep(float* sb, int tid) {
    for (int l = 11; l >= 0; l--) {
        int sz = SS >> l;
        int o  = c_off[l], ou = c_off[l+1];
        for (int i = tid; i < sz; i += 512) {
            float v;
            if (i & 1)          v = sb[ou + (i >> 1)];
            else if (i == 0)    v = sb[o];
            else                v = sb[ou + (i >> 1) - 1] + sb[o + i];
            sb[o + i] = v;
        }
        __syncthreads();
    }
}

__global__ __launch_bounds__(512)
void scan_kernel(const int* __restrict__ tl, float* __restrict__ alpha_sum_out) {
    __shared__ float sb[8192];
    int b   = blockIdx.x;
    int tid = threadIdx.x;

    for (int s = tid; s < SS; s += 512) sb[s] = g_sig[b * SS + s];
    __syncthreads();

    downsweep(sb, tid);
    float asum = sb[c_off[12]];
    if (tid == 0) alpha_sum_out[b] = asum;
    float tlf = (float)tl[b];
    __syncthreads();

    for (int s = tid; s < SS; s += 512) {
        float sc = (sb[s] * tlf) / asum;
        sb[s] = sc;
        g_alpha[b * SS + s] = sc;
    }
    __syncthreads();

    downsweep(sb, tid);
    upsweep(sb, tid);

    for (int s = tid; s < SS; s += 512) {
        float c = sb[s];
        g_csum[b * SS + s] = c;
        g_f  [b * SS + s] = (int)floorf(c + 1e-4f);
    }
}

// ---------------- Phase 1c: W -> bf16 hi/lo, row-major [n][k] -----------------------
__global__ void prep_w_kernel(const float* __restrict__ W) {
    int i = blockIdx.x * 256 + threadIdx.x;
    if (i >= 512 * 512) return;
    int n = i >> 9;
    int k = i & 511;
    float v = (k < 511) ? W[n * 511 + k] : 0.0f;
    __nv_bfloat16 hi = __float2bfloat16(v);
    __nv_bfloat16 lo = __float2bfloat16(v - __bfloat162float(hi));
    g_Bh[i] = hi;
    g_Bl[i] = lo;
}

// ---------------- Phase 2: gather, TT=4, float4 even/odd split, MLP-8x16B -----------
#define TT 4

__global__ __launch_bounds__(256)
void gather_kernel(const float* __restrict__ x) {
    int blk = blockIdx.x;              // b * 128 + tg
    int b   = blk >> 7;
    int tg  = blk & 127;
    int t0  = tg * TT;
    const int*   f  = g_f     + b * SS;
    const float* al = g_alpha + b * SS;
    const float* cs = g_csum  + b * SS;

    int lo, hi;
    {
        int l = 0, r = SS;
        while (l < r) { int m = (l + r) >> 1; if (f[m] >= t0 - 1) r = m; else l = m + 1; }
        lo = l;
        l = 0; r = SS;
        while (l < r) { int m = (l + r) >> 1; if (f[m] > t0 + TT - 1) r = m; else l = m + 1; }
        hi = (l < SS - 1) ? l : SS - 1;
    }

    __shared__ float4 wbuf[160];       // [row] -> weights for 4 t's; [128..159] zero pad
    __shared__ float4 red[TT][128];    // odd-half partial sums
    int tid  = threadIdx.x;
    int half = tid >> 7;               // 0: even rows, 1: odd rows
    int l128 = tid & 127;
    int c0   = l128 * 4;               // channels c0..c0+3
    float4 acc[TT];
    #pragma unroll
    for (int tt = 0; tt < TT; tt++) acc[tt] = make_float4(0.f, 0.f, 0.f, 0.f);

    if (tid >= 128 && tid < 160) wbuf[tid] = make_float4(0.f, 0.f, 0.f, 0.f);

    for (int base = lo; base <= hi; base += 128) {
        if (tid < 128) {
            int s = base + tid;
            float4 wv = make_float4(0.f, 0.f, 0.f, 0.f);
            if (s <= hi) {
                int   d1   = f[s];
                int   d0   = (s == 0) ? 0 : f[s - 1];
                int   fire = d1 - d0;
                float a    = al[s];
                float c    = cs[s];
                float ex   = (fire > 1) ? (float)(fire - 1) : 0.f;
                float rw   = (fire > 0) ? (c - (float)d1) : a;
                float lw   = (a - rw) - ex;
                int   ei   = d0 + 1; if (ei > TMAX - 1) ei = TMAX - 1;
                float exc  = fminf(ex, 1.0f);
                float w[TT];
                #pragma unroll
                for (int tt = 0; tt < TT; tt++) {
                    int t = t0 + tt;
                    float ww = 0.f;
                    if (d1 == t) ww += rw;
                    if (d0 == t) ww += lw;
                    if (ei == t) ww += exc;
                    if (t >= d0 + 2 && t < d1) ww = 1.0f;   // fill overwrite
                    w[tt] = ww;
                }
                wv = make_float4(w[0], w[1], w[2], w[3]);
            }
            wbuf[tid] = wv;
        }
        __syncthreads();

        int n = hi - base + 1; if (n > 128) n = 128;
        const float* xp = x + (size_t)base * (BB*CC) + b * CC + c0;

        // pipeline: this thread streams rows (2q + half); 8 x 16B in flight
        float4 v[8];
        #pragma unroll
        for (int q = 0; q < 8; q++) {
            int r = 2*q + half; r = r < n ? r : n - 1;
            v[q] = *(const float4*)(xp + (size_t)r * (BB*CC));
        }
        for (int jj = 0; jj < n; jj += 16) {
            float4 nv[8];
            #pragma unroll
            for (int q = 0; q < 8; q++) {
                int r = jj + 16 + 2*q + half; r = r < n ? r : n - 1;
                nv[q] = *(const float4*)(xp + (size_t)r * (BB*CC));
            }
            #pragma unroll
            for (int q = 0; q < 8; q++) {
                float4 wq = wbuf[jj + 2*q + half];   // zero beyond window
                acc[0].x += wq.x * v[q].x; acc[0].y += wq.x * v[q].y;
                acc[0].z += wq.x * v[q].z; acc[0].w += wq.x * v[q].w;
                acc[1].x += wq.y * v[q].x; acc[1].y += wq.y * v[q].y;
                acc[1].z += wq.y * v[q].z; acc[1].w += wq.y * v[q].w;
                acc[2].x += wq.z * v[q].x; acc[2].y += wq.z * v[q].y;
                acc[2].z += wq.z * v[q].z; acc[2].w += wq.z * v[q].w;
                acc[3].x += wq.w * v[q].x; acc[3].y += wq.w * v[q].y;
                acc[3].z += wq.w * v[q].z; acc[3].w += wq.w * v[q].w;
            }
            #pragma unroll
            for (int q = 0; q < 8; q++) v[q] = nv[q];
        }
        __syncthreads();
    }

    // combine halves: acc_total = even_total + odd_total
    if (half == 1) {
        #pragma unroll
        for (int tt = 0; tt < TT; tt++) red[tt][l128] = acc[tt];
    }
    __syncthreads();
    if (half == 0) {
        #pragma unroll
        for (int tt = 0; tt < TT; tt++) {
            float4 o = red[tt][l128];
            float4 a = acc[tt];
            a.x += o.x; a.y += o.y; a.z += o.z; a.w += o.w;
            if (l128 == 127) a.w = 0.f;   // channel 511 excluded
            __nv_bfloat16 h0 = __float2bfloat16(a.x), h1 = __float2bfloat16(a.y);
            __nv_bfloat16 h2 = __float2bfloat16(a.z), h3 = __float2bfloat16(a.w);
            __nv_bfloat16 l0 = __float2bfloat16(a.x - __bfloat162float(h0));
            __nv_bfloat16 l1 = __float2bfloat16(a.y - __bfloat162float(h1));
            __nv_bfloat16 l2 = __float2bfloat16(a.z - __bfloat162float(h2));
            __nv_bfloat16 l3 = __float2bfloat16(a.w - __bfloat162float(h3));
            uint2 uh, ul;
            uh.x = (unsigned)__bfloat16_as_ushort(h0) | ((unsigned)__bfloat16_as_ushort(h1) << 16);
            uh.y = (unsigned)__bfloat16_as_ushort(h2) | ((unsigned)__bfloat16_as_ushort(h3) << 16);
            ul.x = (unsigned)__bfloat16_as_ushort(l0) | ((unsigned)__bfloat16_as_ushort(l1) << 16);
            ul.y = (unsigned)__bfloat16_as_ushort(l2) | ((unsigned)__bfloat16_as_ushort(l3) << 16);
            size_t o2 = (size_t)(b * 512 + t0 + tt) * 512 + c0;
            *(uint2*)&g_Ah[o2] = uh;
            *(uint2*)&g_Al[o2] = ul;
        }
    }
}

// ---------------- Phase 3: bf16 split GEMM, mma.sync + ldmatrix + cp.async ----------
#define GBM 128
#define GBN 128
#define GBK 32
#define AST 40
#define BUF_ELEMS (128 * AST)
#define SMEM_GEMM (2 * 4 * BUF_ELEMS * 2)   // 81920

__device__ __forceinline__ uint32_t sm32(const void* p) {
    uint32_t a;
    asm("{ .reg .u64 t; cvta.to.shared.u64 t, %1; cvt.u32.u64 %0, t; }" : "=r"(a) : "l"(p));
    return a;
}
__device__ __forceinline__ void cpa16(uint32_t dst, const void* src) {
    asm volatile("cp.async.cg.shared.global [%0], [%1], 16;" :: "r"(dst), "l"(src) : "memory");
}
__device__ __forceinline__ void ldsm4(uint32_t* r, uint32_t addr) {
    asm volatile("ldmatrix.sync.aligned.m8n8.x4.shared.b16 {%0,%1,%2,%3}, [%4];"
        : "=r"(r[0]), "=r"(r[1]), "=r"(r[2]), "=r"(r[3]) : "r"(addr));
}
__device__ __forceinline__ void mma16816(float* c, const uint32_t* a, const uint32_t* b) {
    asm volatile("mma.sync.aligned.m16n8k16.row.col.f32.bf16.bf16.f32 "
        "{%0,%1,%2,%3}, {%4,%5,%6,%7}, {%8,%9}, {%0,%1,%2,%3};"
        : "+f"(c[0]), "+f"(c[1]), "+f"(c[2]), "+f"(c[3])
        : "r"(a[0]), "r"(a[1]), "r"(a[2]), "r"(a[3]), "r"(b[0]), "r"(b[1]));
}

extern __shared__ __align__(16) __nv_bfloat16 dsm[];

__global__ __launch_bounds__(256, 2)
void gemm_kernel(const float* __restrict__ bias, const int* __restrict__ tl,
                 float* __restrict__ out) {
    int tid  = threadIdx.x;
    int wid  = tid >> 5, lane = tid & 31;
    int wm   = wid & 1,  wn   = wid >> 1;       // warp grid 2 x 4
    int bm   = blockIdx.x * GBM;
    int bn   = blockIdx.y * GBN;
    int lq   = lane >> 2;
    int lr   = lane & 3;

    // all-zero M-block skip: rows t > tl[b] have zero feats -> out = bias
    {
        int bb  = bm >> 9;
        int t0b = bm & 511;
        if (t0b > tl[bb]) {
            int rowi = tid >> 1;
            int cq   = (tid & 1) * 64;
            int t    = t0b + rowi;
            float* op = out + (size_t)t * (BB * CC) + bb * CC + bn + cq;
            const float* bp = bias + bn + cq;
            #pragma unroll
            for (int j = 0; j < 64; j += 4)
                *(float4*)(op + j) = *(const float4*)(bp + j);
            return;
        }
    }

    int crow = tid >> 1;
    int ckq  = (tid & 1) * 16;

    uint32_t smb = sm32(dsm);

    int arow = (lane & 7) + ((lane >> 3) & 1) * 8;
    int akc  = (lane >> 4) * 8;
    int bnof = (lane >> 4) * 8 + (lane & 7);
    int bkc  = ((lane >> 3) & 1) * 8;

    float acc[4][4][4];
    #pragma unroll
    for (int mi = 0; mi < 4; mi++)
        #pragma unroll
        for (int ni = 0; ni < 4; ni++)
            #pragma unroll
            for (int q = 0; q < 4; q++) acc[mi][ni][q] = 0.f;

    const __nv_bfloat16* gA  = g_Ah + (size_t)(bm + crow) * 512 + ckq;
    const __nv_bfloat16* gAl = g_Al + (size_t)(bm + crow) * 512 + ckq;
    const __nv_bfloat16* gB  = g_Bh + (size_t)(bn + crow) * 512 + ckq;
    const __nv_bfloat16* gBl = g_Bl + (size_t)(bn + crow) * 512 + ckq;

    #define ISSUE_STAGE(c, st) do {                                              \
        int k0 = (c) * GBK;                                                      \
        uint32_t dbase = smb + (uint32_t)((((st)*4)*128 + crow)*AST + ckq) * 2;   \
        cpa16(dbase,                        gA  + k0);                            \
        cpa16(dbase + 16,                   gA  + k0 + 8);                        \
        cpa16(dbase + BUF_ELEMS*2,          gAl + k0);                            \
        cpa16(dbase + BUF_ELEMS*2 + 16,     gAl + k0 + 8);                        \
        cpa16(dbase + 2*BUF_ELEMS*2,        gB  + k0);                            \
        cpa16(dbase + 2*BUF_ELEMS*2 + 16,   gB  + k0 + 8);                        \
        cpa16(dbase + 3*BUF_ELEMS*2,        gBl + k0);                            \
        cpa16(dbase + 3*BUF_ELEMS*2 + 16,   gBl + k0 + 8);                        \
    } while (0)

    ISSUE_STAGE(0, 0);
    asm volatile("cp.async.commit_group;" ::: "memory");
    ISSUE_STAGE(1, 1);
    asm volatile("cp.async.commit_group;" ::: "memory");

    for (int c = 0; c < 16; c++) {
        int st = c & 1;
        asm volatile("cp.async.wait_group 1;" ::: "memory");
        __syncthreads();

        uint32_t sAh = smb + (uint32_t)((st*4 + 0) * BUF_ELEMS) * 2;
        uint32_t sAl = smb + (uint32_t)((st*4 + 1) * BUF_ELEMS) * 2;
        uint32_t sBh = smb + (uint32_t)((st*4 + 2) * BUF_ELEMS) * 2;
        uint32_t sBl = smb + (uint32_t)((st*4 + 3) * BUF_ELEMS) * 2;

        #pragma unroll
        for (int ks = 0; ks < 2; ks++) {
            int kb = ks * 16;
            uint32_t bh[4][2], bl[4][2];
            #pragma unroll
            for (int nip = 0; nip < 2; nip++) {
                int ncol = wn * 32 + nip * 16 + bnof;
                uint32_t off = (uint32_t)(ncol * AST + kb + bkc) * 2;
                uint32_t r[4];
                ldsm4(r, sBh + off);
                bh[nip*2+0][0] = r[0]; bh[nip*2+0][1] = r[1];
                bh[nip*2+1][0] = r[2]; bh[nip*2+1][1] = r[3];
                ldsm4(r, sBl + off);
                bl[nip*2+0][0] = r[0]; bl[nip*2+0][1] = r[1];
                bl[nip*2+1][0] = r[2]; bl[nip*2+1][1] = r[3];
            }
            #pragma unroll
            for (int mi = 0; mi < 4; mi++) {
                int row = wm * 64 + mi * 16 + arow;
                uint32_t off = (uint32_t)(row * AST + kb + akc) * 2;
                uint32_t a[4];
                ldsm4(a, sAh + off);
                #pragma unroll
                for (int ni = 0; ni < 4; ni++) mma16816(acc[mi][ni], a, bh[ni]);
                #pragma unroll
                for (int ni = 0; ni < 4; ni++) mma16816(acc[mi][ni], a, bl[ni]);
                ldsm4(a, sAl + off);
                #pragma unroll
                for (int ni = 0; ni < 4; ni++) mma16816(acc[mi][ni], a, bh[ni]);
            }
        }
        __syncthreads();

        if (c + 2 < 16) ISSUE_STAGE(c + 2, st);
        asm volatile("cp.async.commit_group;" ::: "memory");
    }

    // epilogue: out layout (T, B, C): idx = t*(B*C) + b*C + n, with m = b*512 + t
    #pragma unroll
    for (int mi = 0; mi < 4; mi++) {
        int mrow = bm + wm * 64 + mi * 16 + lq;
        #pragma unroll
        for (int half = 0; half < 2; half++) {
            int m = mrow + half * 8;
            int b = m >> 9;
            int t = m & 511;
            float* op = out + (size_t)t * (BB * CC) + b * CC + bn;
            #pragma unroll
            for (int ni = 0; ni < 4; ni++) {
                int nloc = wn * 32 + ni * 8 + lr * 2;
                float2 v;
                v.x = acc[mi][ni][half * 2 + 0] + bias[bn + nloc];
                v.y = acc[mi][ni][half * 2 + 1] + bias[bn + nloc + 1];
                *(float2*)(op + nloc) = v;
            }
        }
    }
}

// ---------------- launch ------------------------------------------------------------
extern "C" void kernel_launch(void* const* d_in, const int* in_sizes, int n_in,
                              void* d_out, int out_size) {
    const float*         x    = (const float*)d_in[0];
    const unsigned char* mask = (const unsigned char*)d_in[1];
    const int*           tl   = (const int*)d_in[2];
    const float*         W    = (const float*)d_in[3];
    const float*         bias = (const float*)d_in[4];
    float*               out  = (float*)d_out;

    float* asum_out = out + (size_t)TMAX * BB * CC;

    cudaFuncSetAttribute(gemm_kernel, cudaFuncAttributeMaxDynamicSharedMemorySize, SMEM_GEMM);

    sigmoid_kernel<<<(BB * SS) / 256, 256>>>(x, mask);
    scan_kernel<<<BB, 512>>>(tl, asum_out);
    prep_w_kernel<<<(512 * 512 + 255) / 256, 256>>>(W);
    gather_kernel<<<BB * 128, 256>>>(x);
    gemm_kernel<<<dim3(8192 / GBM, 512 / GBN), 256, SMEM_GEMM>>>(bias, tl, out);
}

// round 11
// speedup vs baseline: 1.0893x; 1.0893x over previous
#include <cuda_runtime.h>
#include <cuda_bf16.h>
#include <math.h>
#include <stdint.h>

// Problem constants
#define SS   4096
#define BB   16
#define CC   512
#define TMAX 512
#define INVN (TMAX + 2)   // 514

// ---------------- device scratch (static; no cudaMalloc) ----------------------------
__device__ float g_sig  [BB * SS];          // raw sigmoid
__device__ float g_alpha[BB * SS];          // scaled alpha
__device__ float g_csum [BB * SS];
__device__ int   g_f    [BB * SS];
__device__ int   g_inv  [BB * INVN];        // inv[t] = first s with f[s] >= t
__device__ __align__(16) __nv_bfloat16 g_Ah[8192 * 512];
__device__ __align__(16) __nv_bfloat16 g_Al[8192 * 512];
__device__ __align__(16) __nv_bfloat16 g_Bh[512 * 512];
__device__ __align__(16) __nv_bfloat16 g_Bl[512 * 512];

__constant__ int c_off[13] = {0,4096,6144,7168,7680,7936,8064,8128,8160,8176,8184,8188,8190};

// ---------------- Phase 1a: fp64 sigmoid spread over the whole chip -----------------
__global__ __launch_bounds__(256)
void sigmoid_kernel(const float* __restrict__ x, const unsigned char* __restrict__ mask) {
    int i = blockIdx.x * 256 + threadIdx.x;    // i = b*SS + s
    int b = i >> 12;
    int s = i & (SS - 1);
    float a = mask[i] ? -10000.0f : x[(size_t)s * (BB*CC) + b * CC + (CC - 1)];
    double sg = 1.0 / (1.0 + exp(-(double)a));
    g_sig[i] = (float)sg;
}

// ---------------- Phase 1b: fp32 reduce + exact JAX-tree cumsum + fire + inv map ----
__device__ __forceinline__ void downsweep(float* sb, int tid) {
    for (int l = 1; l <= 12; l++) {
        int sz = SS >> l;
        int o  = c_off[l], oi = c_off[l-1];
        for (int i = tid; i < sz; i += 512)
            sb[o + i] = sb[oi + 2*i] + sb[oi + 2*i + 1];
        __syncthreads();
    }
}
__device__ __forceinline__ void upsweep(float* sb, int tid) {
    for (int l = 11; l >= 0; l--) {
        int sz = SS >> l;
        int o  = c_off[l], ou = c_off[l+1];
        for (int i = tid; i < sz; i += 512) {
            float v;
            if (i & 1)          v = sb[ou + (i >> 1)];
            else if (i == 0)    v = sb[o];
            else                v = sb[ou + (i >> 1) - 1] + sb[o + i];
            sb[o + i] = v;
        }
        __syncthreads();
    }
}

__global__ __launch_bounds__(512)
void scan_kernel(const int* __restrict__ tl, float* __restrict__ alpha_sum_out) {
    __shared__ float sb[8192];
    int b   = blockIdx.x;
    int tid = threadIdx.x;

    for (int s = tid; s < SS; s += 512) sb[s] = g_sig[b * SS + s];
    __syncthreads();

    downsweep(sb, tid);
    float asum = sb[c_off[12]];
    if (tid == 0) alpha_sum_out[b] = asum;
    float tlf = (float)tl[b];
    __syncthreads();

    for (int s = tid; s < SS; s += 512) {
        float sc = (sb[s] * tlf) / asum;
        sb[s] = sc;
        g_alpha[b * SS + s] = sc;
    }
    __syncthreads();

    downsweep(sb, tid);
    upsweep(sb, tid);

    for (int s = tid; s < SS; s += 512) {
        float c = sb[s];
        g_csum[b * SS + s] = c;
        g_f  [b * SS + s] = (int)floorf(c + 1e-4f);
    }

    // ---- build inverse map: inv[t] = first s with f[s] >= t ----
    for (int i = tid; i < INVN; i += 512)
        g_inv[b * INVN + i] = (i == 0) ? 0 : SS;
    __syncthreads();
    for (int s = tid; s < SS; s += 512) {
        int d1 = (int)floorf(sb[s] + 1e-4f);
        int d0 = (s == 0) ? 0 : (int)floorf(sb[s - 1] + 1e-4f);
        int te = d1 < (INVN - 1) ? d1 : (INVN - 1);
        for (int t = d0 + 1; t <= te; t++)
            g_inv[b * INVN + t] = s;     // disjoint ranges: no race
    }
}

// ---------------- Phase 1c: W -> bf16 hi/lo, row-major [n][k] -----------------------
__global__ void prep_w_kernel(const float* __restrict__ W) {
    int i = blockIdx.x * 256 + threadIdx.x;
    if (i >= 512 * 512) return;
    int n = i >> 9;
    int k = i & 511;
    float v = (k < 511) ? W[n * 511 + k] : 0.0f;
    __nv_bfloat16 hi = __float2bfloat16(v);
    __nv_bfloat16 lo = __float2bfloat16(v - __bfloat162float(hi));
    g_Bh[i] = hi;
    g_Bl[i] = lo;
}

// ---------------- Phase 2: gather, TT=4, inv-table windows, MLP-8 float2 stream -----
#define TT 4

__global__ __launch_bounds__(256)
void gather_kernel(const float* __restrict__ x) {
    int blk = blockIdx.x;              // b * 128 + tg
    int b   = blk >> 7;
    int tg  = blk & 127;
    int t0  = tg * TT;
    const int*   f  = g_f     + b * SS;
    const float* al = g_alpha + b * SS;
    const float* cs = g_csum  + b * SS;
    const int*   iv = g_inv   + b * INVN;

    // O(1) window from inverse map (replaces two binary searches)
    int lo  = (t0 == 0) ? 0 : iv[t0 - 1];
    int hiv = iv[t0 + TT];
    int hi  = (hiv < SS - 1) ? hiv : SS - 1;

    __shared__ float4 wbuf[144];       // [row] -> weights for 4 t's; [128..143] zero pad
    int tid = threadIdx.x;
    int c0  = tid * 2;                 // global channel of .x (0..510)
    float2 acc[TT];
    #pragma unroll
    for (int tt = 0; tt < TT; tt++) acc[tt] = make_float2(0.f, 0.f);

    if (tid >= 128 && tid < 144) wbuf[tid] = make_float4(0.f, 0.f, 0.f, 0.f);

    for (int base = lo; base <= hi; base += 128) {
        if (tid < 128) {
            int s = base + tid;
            float4 wv = make_float4(0.f, 0.f, 0.f, 0.f);
            if (s <= hi) {
                int   d1   = f[s];
                int   d0   = (s == 0) ? 0 : f[s - 1];
                int   fire = d1 - d0;
                float a    = al[s];
                float c    = cs[s];
                float ex   = (fire > 1) ? (float)(fire - 1) : 0.f;
                float rw   = (fire > 0) ? (c - (float)d1) : a;
                float lw   = (a - rw) - ex;
                int   ei   = d0 + 1; if (ei > TMAX - 1) ei = TMAX - 1;
                float exc  = fminf(ex, 1.0f);
                float w[TT];
                #pragma unroll
                for (int tt = 0; tt < TT; tt++) {
                    int t = t0 + tt;
                    float ww = 0.f;
                    if (d1 == t) ww += rw;
                    if (d0 == t) ww += lw;
                    if (ei == t) ww += exc;
                    if (t >= d0 + 2 && t < d1) ww = 1.0f;   // fill overwrite
                    w[tt] = ww;
                }
                wv = make_float4(w[0], w[1], w[2], w[3]);
            }
            wbuf[tid] = wv;
        }
        __syncthreads();

        int n = hi - base + 1; if (n > 128) n = 128;
        const float* xp = x + (size_t)base * (BB*CC) + b * CC + c0;

        // software-pipelined: 8 rows in flight + 8 prefetched (clamped; pad weight=0)
        float2 v[8];
        #pragma unroll
        for (int q = 0; q < 8; q++) {
            int r = q < n ? q : n - 1;
            v[q] = *(const float2*)(xp + (size_t)r * (BB*CC));
        }
        for (int j = 0; j < n; j += 8) {
            float2 nv[8];
            #pragma unroll
            for (int q = 0; q < 8; q++) {
                int r = j + 8 + q; r = r < n ? r : n - 1;
                nv[q] = *(const float2*)(xp + (size_t)r * (BB*CC));
            }
            #pragma unroll
            for (int q = 0; q < 8; q++) {
                float4 wq = wbuf[j + q];
                acc[0].x += wq.x * v[q].x; acc[0].y += wq.x * v[q].y;
                acc[1].x += wq.y * v[q].x; acc[1].y += wq.y * v[q].y;
                acc[2].x += wq.z * v[q].x; acc[2].y += wq.z * v[q].y;
                acc[3].x += wq.w * v[q].x; acc[3].y += wq.w * v[q].y;
            }
            #pragma unroll
            for (int q = 0; q < 8; q++) v[q] = nv[q];
        }
        __syncthreads();
    }

    // emit bf16 hi/lo
    #pragma unroll
    for (int tt = 0; tt < TT; tt++) {
        float2 a = acc[tt];
        if (c0 == 510) a.y = 0.f;   // channel 511 excluded
        __nv_bfloat16 h0 = __float2bfloat16(a.x), h1 = __float2bfloat16(a.y);
        __nv_bfloat16 l0 = __float2bfloat16(a.x - __bfloat162float(h0));
        __nv_bfloat16 l1 = __float2bfloat16(a.y - __bfloat162float(h1));
        uint32_t uh = (unsigned)__bfloat16_as_ushort(h0) | ((unsigned)__bfloat16_as_ushort(h1) << 16);
        uint32_t ul = (unsigned)__bfloat16_as_ushort(l0) | ((unsigned)__bfloat16_as_ushort(l1) << 16);
        size_t o = (size_t)(b * 512 + t0 + tt) * 512 + c0;
        *(uint32_t*)&g_Ah[o] = uh;
        *(uint32_t*)&g_Al[o] = ul;
    }
}

// ---------------- Phase 3: bf16 split GEMM, mma.sync + ldmatrix + cp.async ----------
#define GBM 128
#define GBN 128
#define GBK 32
#define AST 40
#define BUF_ELEMS (128 * AST)
#define SMEM_GEMM (2 * 4 * BUF_ELEMS * 2)   // 81920

__device__ __forceinline__ uint32_t sm32(const void* p) {
    uint32_t a;
    asm("{ .reg .u64 t; cvta.to.shared.u64 t, %1; cvt.u32.u64 %0, t; }" : "=r"(a) : "l"(p));
    return a;
}
__device__ __forceinline__ void cpa16(uint32_t dst, const void* src) {
    asm volatile("cp.async.cg.shared.global [%0], [%1], 16;" :: "r"(dst), "l"(src) : "memory");
}
__device__ __forceinline__ void ldsm4(uint32_t* r, uint32_t addr) {
    asm volatile("ldmatrix.sync.aligned.m8n8.x4.shared.b16 {%0,%1,%2,%3}, [%4];"
        : "=r"(r[0]), "=r"(r[1]), "=r"(r[2]), "=r"(r[3]) : "r"(addr));
}
__device__ __forceinline__ void mma16816(float* c, const uint32_t* a, const uint32_t* b) {
    asm volatile("mma.sync.aligned.m16n8k16.row.col.f32.bf16.bf16.f32 "
        "{%0,%1,%2,%3}, {%4,%5,%6,%7}, {%8,%9}, {%0,%1,%2,%3};"
        : "+f"(c[0]), "+f"(c[1]), "+f"(c[2]), "+f"(c[3])
        : "r"(a[0]), "r"(a[1]), "r"(a[2]), "r"(a[3]), "r"(b[0]), "r"(b[1]));
}

extern __shared__ __align__(16) __nv_bfloat16 dsm[];

__global__ __launch_bounds__(256, 2)
void gemm_kernel(const float* __restrict__ bias, const int* __restrict__ tl,
                 float* __restrict__ out) {
    int tid  = threadIdx.x;
    int wid  = tid >> 5, lane = tid & 31;
    int wm   = wid & 1,  wn   = wid >> 1;       // warp grid 2 x 4
    int bm   = blockIdx.x * GBM;
    int bn   = blockIdx.y * GBN;
    int lq   = lane >> 2;
    int lr   = lane & 3;

    // all-zero M-block skip: rows t > tl[b] have zero feats -> out = bias
    {
        int bb  = bm >> 9;
        int t0b = bm & 511;
        if (t0b > tl[bb]) {
            int rowi = tid >> 1;
            int cq   = (tid & 1) * 64;
            int t    = t0b + rowi;
            float* op = out + (size_t)t * (BB * CC) + bb * CC + bn + cq;
            const float* bp = bias + bn + cq;
            #pragma unroll
            for (int j = 0; j < 64; j += 4)
                *(float4*)(op + j) = *(const float4*)(bp + j);
            return;
        }
    }

    int crow = tid >> 1;
    int ckq  = (tid & 1) * 16;

    uint32_t smb = sm32(dsm);

    int arow = (lane & 7) + ((lane >> 3) & 1) * 8;
    int akc  = (lane >> 4) * 8;
    int bnof = (lane >> 4) * 8 + (lane & 7);
    int bkc  = ((lane >> 3) & 1) * 8;

    float acc[4][4][4];
    #pragma unroll
    for (int mi = 0; mi < 4; mi++)
        #pragma unroll
        for (int ni = 0; ni < 4; ni++)
            #pragma unroll
            for (int q = 0; q < 4; q++) acc[mi][ni][q] = 0.f;

    const __nv_bfloat16* gA  = g_Ah + (size_t)(bm + crow) * 512 + ckq;
    const __nv_bfloat16* gAl = g_Al + (size_t)(bm + crow) * 512 + ckq;
    const __nv_bfloat16* gB  = g_Bh + (size_t)(bn + crow) * 512 + ckq;
    const __nv_bfloat16* gBl = g_Bl + (size_t)(bn + crow) * 512 + ckq;

    #define ISSUE_STAGE(c, st) do {                                              \
        int k0 = (c) * GBK;                                                      \
        uint32_t dbase = smb + (uint32_t)((((st)*4)*128 + crow)*AST + ckq) * 2;   \
        cpa16(dbase,                        gA  + k0);                            \
        cpa16(dbase + 16,                   gA  + k0 + 8);                        \
        cpa16(dbase + BUF_ELEMS*2,          gAl + k0);                            \
        cpa16(dbase + BUF_ELEMS*2 + 16,     gAl + k0 + 8);                        \
        cpa16(dbase + 2*BUF_ELEMS*2,        gB  + k0);                            \
        cpa16(dbase + 2*BUF_ELEMS*2 + 16,   gB  + k0 + 8);                        \
        cpa16(dbase + 3*BUF_ELEMS*2,        gBl + k0);                            \
        cpa16(dbase + 3*BUF_ELEMS*2 + 16,   gBl + k0 + 8);                        \
    } while (0)

    ISSUE_STAGE(0, 0);
    asm volatile("cp.async.commit_group;" ::: "memory");
    ISSUE_STAGE(1, 1);
    asm volatile("cp.async.commit_group;" ::: "memory");

    for (int c = 0; c < 16; c++) {
        int st = c & 1;
        asm volatile("cp.async.wait_group 1;" ::: "memory");
        __syncthreads();

        uint32_t sAh = smb + (uint32_t)((st*4 + 0) * BUF_ELEMS) * 2;
        uint32_t sAl = smb + (uint32_t)((st*4 + 1) * BUF_ELEMS) * 2;
        uint32_t sBh = smb + (uint32_t)((st*4 + 2) * BUF_ELEMS) * 2;
        uint32_t sBl = smb + (uint32_t)((st*4 + 3) * BUF_ELEMS) * 2;

        #pragma unroll
        for (int ks = 0; ks < 2; ks++) {
            int kb = ks * 16;
            uint32_t bh[4][2], bl[4][2];
            #pragma unroll
            for (int nip = 0; nip < 2; nip++) {
                int ncol = wn * 32 + nip * 16 + bnof;
                uint32_t off = (uint32_t)(ncol * AST + kb + bkc) * 2;
                uint32_t r[4];
                ldsm4(r, sBh + off);
                bh[nip*2+0][0] = r[0]; bh[nip*2+0][1] = r[1];
                bh[nip*2+1][0] = r[2]; bh[nip*2+1][1] = r[3];
                ldsm4(r, sBl + off);
                bl[nip*2+0][0] = r[0]; bl[nip*2+0][1] = r[1];
                bl[nip*2+1][0] = r[2]; bl[nip*2+1][1] = r[3];
            }
            #pragma unroll
            for (int mi = 0; mi < 4; mi++) {
                int row = wm * 64 + mi * 16 + arow;
                uint32_t off = (uint32_t)(row * AST + kb + akc) * 2;
                uint32_t a[4];
                ldsm4(a, sAh + off);
                #pragma unroll
                for (int ni = 0; ni < 4; ni++) mma16816(acc[mi][ni], a, bh[ni]);
                #pragma unroll
                for (int ni = 0; ni < 4; ni++) mma16816(acc[mi][ni], a, bl[ni]);
                ldsm4(a, sAl + off);
                #pragma unroll
                for (int ni = 0; ni < 4; ni++) mma16816(acc[mi][ni], a, bh[ni]);
            }
        }
        __syncthreads();

        if (c + 2 < 16) ISSUE_STAGE(c + 2, st);
        asm volatile("cp.async.commit_group;" ::: "memory");
    }

    // epilogue: out layout (T, B, C): idx = t*(B*C) + b*C + n, with m = b*512 + t
    #pragma unroll
    for (int mi = 0; mi < 4; mi++) {
        int mrow = bm + wm * 64 + mi * 16 + lq;
        #pragma unroll
        for (int half = 0; half < 2; half++) {
            int m = mrow + half * 8;
            int b = m >> 9;
            int t = m & 511;
            float* op = out + (size_t)t * (BB * CC) + b * CC + bn;
            #pragma unroll
            for (int ni = 0; ni < 4; ni++) {
                int nloc = wn * 32 + ni * 8 + lr * 2;
                float2 v;
                v.x = acc[mi][ni][half * 2 + 0] + bias[bn + nloc];
                v.y = acc[mi][ni][half * 2 + 1] + bias[bn + nloc + 1];
                *(float2*)(op + nloc) = v;
            }
        }
    }
}

// ---------------- launch ------------------------------------------------------------
extern "C" void kernel_launch(void* const* d_in, const int* in_sizes, int n_in,
                              void* d_out, int out_size) {
    const float*         x    = (const float*)d_in[0];
    const unsigned char* mask = (const unsigned char*)d_in[1];
    const int*           tl   = (const int*)d_in[2];
    const float*         W    = (const float*)d_in[3];
    const float*         bias = (const float*)d_in[4];
    float*               out  = (float*)d_out;

    float* asum_out = out + (size_t)TMAX * BB * CC;

    cudaFuncSetAttribute(gemm_kernel, cudaFuncAttributeMaxDynamicSharedMemorySize, SMEM_GEMM);

    sigmoid_kernel<<<(BB * SS) / 256, 256>>>(x, mask);
    scan_kernel<<<BB, 512>>>(tl, asum_out);
    prep_w_kernel<<<(512 * 512 + 255) / 256, 256>>>(W);
    gather_kernel<<<BB * 128, 256>>>(x);
    gemm_kernel<<<dim3(8192 / GBM, 512 / GBN), 256, SMEM_GEMM>>>(bias, tl, out);
}

// round 12
// speedup vs baseline: 1.2673x; 1.1635x over previous
#include <cuda_runtime.h>
#include <cuda_fp16.h>
#include <math.h>
#include <stdint.h>

// Problem constants
#define SS   4096
#define BB   16
#define CC   512
#define TMAX 512
#define INVN (TMAX + 2)   // 514

// ---------------- device scratch (static; no cudaMalloc) ----------------------------
__device__ float g_sig  [BB * SS];          // raw sigmoid
__device__ float g_alpha[BB * SS];          // scaled alpha
__device__ float g_csum [BB * SS];
__device__ int   g_f    [BB * SS];
__device__ int   g_inv  [BB * INVN];        // inv[t] = first s with f[s] >= t
__device__ __align__(16) __half g_Ah[8192 * 512];
__device__ __align__(16) __half g_Al[8192 * 512];
__device__ __align__(16) __half g_Bh[512 * 512];

__constant__ int c_off[13] = {0,4096,6144,7168,7680,7936,8064,8128,8160,8176,8184,8188,8190};

// ---------------- Phase 1a: fp64 sigmoid spread over the whole chip -----------------
__global__ __launch_bounds__(256)
void sigmoid_kernel(const float* __restrict__ x, const unsigned char* __restrict__ mask) {
    int i = blockIdx.x * 256 + threadIdx.x;    // i = b*SS + s
    int b = i >> 12;
    int s = i & (SS - 1);
    float a = mask[i] ? -10000.0f : x[(size_t)s * (BB*CC) + b * CC + (CC - 1)];
    double sg = 1.0 / (1.0 + exp(-(double)a));
    g_sig[i] = (float)sg;
}

// ---------------- Phase 1b: fp32 reduce + exact JAX-tree cumsum + fire + inv map ----
__device__ __forceinline__ void downsweep(float* sb, int tid) {
    for (int l = 1; l <= 12; l++) {
        int sz = SS >> l;
        int o  = c_off[l], oi = c_off[l-1];
        for (int i = tid; i < sz; i += 512)
            sb[o + i] = sb[oi + 2*i] + sb[oi + 2*i + 1];
        __syncthreads();
    }
}
__device__ __forceinline__ void upsweep(float* sb, int tid) {
    for (int l = 11; l >= 0; l--) {
        int sz = SS >> l;
        int o  = c_off[l], ou = c_off[l+1];
        for (int i = tid; i < sz; i += 512) {
            float v;
            if (i & 1)          v = sb[ou + (i >> 1)];
            else if (i == 0)    v = sb[o];
            else                v = sb[ou + (i >> 1) - 1] + sb[o + i];
            sb[o + i] = v;
        }
        __syncthreads();
    }
}

__global__ __launch_bounds__(512)
void scan_kernel(const int* __restrict__ tl, float* __restrict__ alpha_sum_out) {
    __shared__ float sb[8192];
    int b   = blockIdx.x;
    int tid = threadIdx.x;

    for (int s = tid; s < SS; s += 512) sb[s] = g_sig[b * SS + s];
    __syncthreads();

    downsweep(sb, tid);
    float asum = sb[c_off[12]];
    if (tid == 0) alpha_sum_out[b] = asum;
    float tlf = (float)tl[b];
    __syncthreads();

    for (int s = tid; s < SS; s += 512) {
        float sc = (sb[s] * tlf) / asum;
        sb[s] = sc;
        g_alpha[b * SS + s] = sc;
    }
    __syncthreads();

    downsweep(sb, tid);
    upsweep(sb, tid);

    for (int s = tid; s < SS; s += 512) {
        float c = sb[s];
        g_csum[b * SS + s] = c;
        g_f  [b * SS + s] = (int)floorf(c + 1e-4f);
    }

    // ---- build inverse map: inv[t] = first s with f[s] >= t ----
    for (int i = tid; i < INVN; i += 512)
        g_inv[b * INVN + i] = (i == 0) ? 0 : SS;
    __syncthreads();
    for (int s = tid; s < SS; s += 512) {
        int d1 = (int)floorf(sb[s] + 1e-4f);
        int d0 = (s == 0) ? 0 : (int)floorf(sb[s - 1] + 1e-4f);
        int te = d1 < (INVN - 1) ? d1 : (INVN - 1);
        for (int t = d0 + 1; t <= te; t++)
            g_inv[b * INVN + t] = s;     // disjoint ranges: no race
    }
}

// ---------------- Phase 1c: W -> fp16, row-major [n][k] -----------------------------
__global__ void prep_w_kernel(const float* __restrict__ W) {
    int i = blockIdx.x * 256 + threadIdx.x;
    if (i >= 512 * 512) return;
    int n = i >> 9;
    int k = i & 511;
    float v = (k < 511) ? W[n * 511 + k] : 0.0f;
    g_Bh[i] = __float2half(v);
}

// ---------------- Phase 2: gather, TT=4, inv-table windows, MLP-8 float2 stream -----
#define TT 4

__global__ __launch_bounds__(256)
void gather_kernel(const float* __restrict__ x) {
    int blk = blockIdx.x;              // b * 128 + tg
    int b   = blk >> 7;
    int tg  = blk & 127;
    int t0  = tg * TT;
    const int*   f  = g_f     + b * SS;
    const float* al = g_alpha + b * SS;
    const float* cs = g_csum  + b * SS;
    const int*   iv = g_inv   + b * INVN;

    // O(1) window from inverse map
    int lo  = (t0 == 0) ? 0 : iv[t0 - 1];
    int hiv = iv[t0 + TT];
    int hi  = (hiv < SS - 1) ? hiv : SS - 1;

    __shared__ float4 wbuf[144];       // [row] -> weights for 4 t's; [128..143] zero pad
    int tid = threadIdx.x;
    int c0  = tid * 2;                 // global channel of .x (0..510)
    float2 acc[TT];
    #pragma unroll
    for (int tt = 0; tt < TT; tt++) acc[tt] = make_float2(0.f, 0.f);

    if (tid >= 128 && tid < 144) wbuf[tid] = make_float4(0.f, 0.f, 0.f, 0.f);

    for (int base = lo; base <= hi; base += 128) {
        if (tid < 128) {
            int s = base + tid;
            float4 wv = make_float4(0.f, 0.f, 0.f, 0.f);
            if (s <= hi) {
                int   d1   = f[s];
                int   d0   = (s == 0) ? 0 : f[s - 1];
                int   fire = d1 - d0;
                float a    = al[s];
                float c    = cs[s];
                float ex   = (fire > 1) ? (float)(fire - 1) : 0.f;
                float rw   = (fire > 0) ? (c - (float)d1) : a;
                float lw   = (a - rw) - ex;
                int   ei   = d0 + 1; if (ei > TMAX - 1) ei = TMAX - 1;
                float exc  = fminf(ex, 1.0f);
                float w[TT];
                #pragma unroll
                for (int tt = 0; tt < TT; tt++) {
                    int t = t0 + tt;
                    float ww = 0.f;
                    if (d1 == t) ww += rw;
                    if (d0 == t) ww += lw;
                    if (ei == t) ww += exc;
                    if (t >= d0 + 2 && t < d1) ww = 1.0f;   // fill overwrite
                    w[tt] = ww;
                }
                wv = make_float4(w[0], w[1], w[2], w[3]);
            }
            wbuf[tid] = wv;
        }
        __syncthreads();

        int n = hi - base + 1; if (n > 128) n = 128;
        const float* xp = x + (size_t)base * (BB*CC) + b * CC + c0;

        // software-pipelined: 8 rows in flight + 8 prefetched (clamped; pad weight=0)
        float2 v[8];
        #pragma unroll
        for (int q = 0; q < 8; q++) {
            int r = q < n ? q : n - 1;
            v[q] = *(const float2*)(xp + (size_t)r * (BB*CC));
        }
        for (int j = 0; j < n; j += 8) {
            float2 nv[8];
            #pragma unroll
            for (int q = 0; q < 8; q++) {
                int r = j + 8 + q; r = r < n ? r : n - 1;
                nv[q] = *(const float2*)(xp + (size_t)r * (BB*CC));
            }
            #pragma unroll
            for (int q = 0; q < 8; q++) {
                float4 wq = wbuf[j + q];
                acc[0].x += wq.x * v[q].x; acc[0].y += wq.x * v[q].y;
                acc[1].x += wq.y * v[q].x; acc[1].y += wq.y * v[q].y;
                acc[2].x += wq.z * v[q].x; acc[2].y += wq.z * v[q].y;
                acc[3].x += wq.w * v[q].x; acc[3].y += wq.w * v[q].y;
            }
            #pragma unroll
            for (int q = 0; q < 8; q++) v[q] = nv[q];
        }
        __syncthreads();
    }

    // emit fp16 hi + residual lo (A exact to ~2^-22)
    #pragma unroll
    for (int tt = 0; tt < TT; tt++) {
        float2 a = acc[tt];
        if (c0 == 510) a.y = 0.f;   // channel 511 excluded
        __half h0 = __float2half(a.x), h1 = __float2half(a.y);
        __half l0 = __float2half(a.x - __half2float(h0));
        __half l1 = __float2half(a.y - __half2float(h1));
        uint32_t uh = (uint32_t)__half_as_ushort(h0) | ((uint32_t)__half_as_ushort(h1) << 16);
        uint32_t ul = (uint32_t)__half_as_ushort(l0) | ((uint32_t)__half_as_ushort(l1) << 16);
        size_t o = (size_t)(b * 512 + t0 + tt) * 512 + c0;
        *(uint32_t*)&g_Ah[o] = uh;
        *(uint32_t*)&g_Al[o] = ul;
    }
}

// ---------------- Phase 3: fp16 2-product GEMM, 3-stage cp.async, 1 sync/chunk ------
#define GBM 128
#define GBN 128
#define GBK 32
#define AST 40
#define BUF_ELEMS (128 * AST)
#define NBUF 3                                   // Ah, Al, Bh
#define SMEM_GEMM (3 * NBUF * BUF_ELEMS * 2)     // 3 stages = 92160

__device__ __forceinline__ uint32_t sm32(const void* p) {
    uint32_t a;
    asm("{ .reg .u64 t; cvta.to.shared.u64 t, %1; cvt.u32.u64 %0, t; }" : "=r"(a) : "l"(p));
    return a;
}
__device__ __forceinline__ void cpa16(uint32_t dst, const void* src) {
    asm volatile("cp.async.cg.shared.global [%0], [%1], 16;" :: "r"(dst), "l"(src) : "memory");
}
__device__ __forceinline__ void ldsm4(uint32_t* r, uint32_t addr) {
    asm volatile("ldmatrix.sync.aligned.m8n8.x4.shared.b16 {%0,%1,%2,%3}, [%4];"
        : "=r"(r[0]), "=r"(r[1]), "=r"(r[2]), "=r"(r[3]) : "r"(addr));
}
__device__ __forceinline__ void mma16816(float* c, const uint32_t* a, const uint32_t* b) {
    asm volatile("mma.sync.aligned.m16n8k16.row.col.f32.f16.f16.f32 "
        "{%0,%1,%2,%3}, {%4,%5,%6,%7}, {%8,%9}, {%0,%1,%2,%3};"
        : "+f"(c[0]), "+f"(c[1]), "+f"(c[2]), "+f"(c[3])
        : "r"(a[0]), "r"(a[1]), "r"(a[2]), "r"(a[3]), "r"(b[0]), "r"(b[1]));
}

extern __shared__ __align__(16) __half dsm[];

__global__ __launch_bounds__(256, 2)
void gemm_kernel(const float* __restrict__ bias, const int* __restrict__ tl,
                 float* __restrict__ out) {
    int tid  = threadIdx.x;
    int wid  = tid >> 5, lane = tid & 31;
    int wm   = wid & 1,  wn   = wid >> 1;       // warp grid 2 x 4
    int bm   = blockIdx.x * GBM;
    int bn   = blockIdx.y * GBN;
    int lq   = lane >> 2;
    int lr   = lane & 3;

    // all-zero M-block skip: rows t > tl[b] have zero feats -> out = bias
    {
        int bb  = bm >> 9;
        int t0b = bm & 511;
        if (t0b > tl[bb]) {
            int rowi = tid >> 1;
            int cq   = (tid & 1) * 64;
            int t    = t0b + rowi;
            float* op = out + (size_t)t * (BB * CC) + bb * CC + bn + cq;
            const float* bp = bias + bn + cq;
            #pragma unroll
            for (int j = 0; j < 64; j += 4)
                *(float4*)(op + j) = *(const float4*)(bp + j);
            return;
        }
    }

    int crow = tid >> 1;
    int ckq  = (tid & 1) * 16;

    uint32_t smb = sm32(dsm);

    int arow = (lane & 7) + ((lane >> 3) & 1) * 8;   // A: row within 16
    int akc  = (lane >> 4) * 8;                      // A: k offset 0/8
    int bnof = (lane >> 4) * 8 + (lane & 7);         // B: n within 16
    int bkc  = ((lane >> 3) & 1) * 8;                // B: k offset 0/8

    float acc[4][4][4];
    #pragma unroll
    for (int mi = 0; mi < 4; mi++)
        #pragma unroll
        for (int ni = 0; ni < 4; ni++)
            #pragma unroll
            for (int q = 0; q < 4; q++) acc[mi][ni][q] = 0.f;

    const __half* gA  = g_Ah + (size_t)(bm + crow) * 512 + ckq;
    const __half* gAl = g_Al + (size_t)(bm + crow) * 512 + ckq;
    const __half* gB  = g_Bh + (size_t)(bn + crow) * 512 + ckq;

    #define ISSUE_STAGE(c, st) do {                                                   \
        int k0 = (c) * GBK;                                                           \
        uint32_t dbase = smb + (uint32_t)((((st)*NBUF)*128 + crow)*AST + ckq) * 2;     \
        cpa16(dbase,                      gA  + k0);                                   \
        cpa16(dbase + 16,                 gA  + k0 + 8);                               \
        cpa16(dbase + BUF_ELEMS*2,        gAl + k0);                                   \
        cpa16(dbase + BUF_ELEMS*2 + 16,   gAl + k0 + 8);                               \
        cpa16(dbase + 2*BUF_ELEMS*2,      gB  + k0);                                   \
        cpa16(dbase + 2*BUF_ELEMS*2 + 16, gB  + k0 + 8);                               \
    } while (0)

    // prologue: 2 stages in flight
    ISSUE_STAGE(0, 0);
    asm volatile("cp.async.commit_group;" ::: "memory");
    ISSUE_STAGE(1, 1);
    asm volatile("cp.async.commit_group;" ::: "memory");

    for (int c = 0; c < 16; c++) {
        int st = c % 3;
        asm volatile("cp.async.wait_group 1;" ::: "memory");
        __syncthreads();   // stage c ready; everyone done reading stage (c+2)%3

        uint32_t sAh = smb + (uint32_t)((st*NBUF + 0) * BUF_ELEMS) * 2;
        uint32_t sAl = smb + (uint32_t)((st*NBUF + 1) * BUF_ELEMS) * 2;
        uint32_t sBh = smb + (uint32_t)((st*NBUF + 2) * BUF_ELEMS) * 2;

        #pragma unroll
        for (int ks = 0; ks < 2; ks++) {
            int kb = ks * 16;
            uint32_t bh[4][2];
            #pragma unroll
            for (int nip = 0; nip < 2; nip++) {
                int ncol = wn * 32 + nip * 16 + bnof;
                uint32_t off = (uint32_t)(ncol * AST + kb + bkc) * 2;
                uint32_t r[4];
                ldsm4(r, sBh + off);
                bh[nip*2+0][0] = r[0]; bh[nip*2+0][1] = r[1];
                bh[nip*2+1][0] = r[2]; bh[nip*2+1][1] = r[3];
            }
            #pragma unroll
            for (int mi = 0; mi < 4; mi++) {
                int row = wm * 64 + mi * 16 + arow;
                uint32_t off = (uint32_t)(row * AST + kb + akc) * 2;
                uint32_t a[4];
                ldsm4(a, sAh + off);
                #pragma unroll
                for (int ni = 0; ni < 4; ni++) mma16816(acc[mi][ni], a, bh[ni]);
                ldsm4(a, sAl + off);
                #pragma unroll
                for (int ni = 0; ni < 4; ni++) mma16816(acc[mi][ni], a, bh[ni]);
            }
        }

        if (c + 2 < 16) ISSUE_STAGE(c + 2, (c + 2) % 3);
        asm volatile("cp.async.commit_group;" ::: "memory");
    }

    // epilogue: out layout (T, B, C): idx = t*(B*C) + b*C + n, with m = b*512 + t
    #pragma unroll
    for (int mi = 0; mi < 4; mi++) {
        int mrow = bm + wm * 64 + mi * 16 + lq;
        #pragma unroll
        for (int half = 0; half < 2; half++) {
            int m = mrow + half * 8;
            int b = m >> 9;
            int t = m & 511;
            float* op = out + (size_t)t * (BB * CC) + b * CC + bn;
            #pragma unroll
            for (int ni = 0; ni < 4; ni++) {
                int nloc = wn * 32 + ni * 8 + lr * 2;
                float2 v;
                v.x = acc[mi][ni][half * 2 + 0] + bias[bn + nloc];
                v.y = acc[mi][ni][half * 2 + 1] + bias[bn + nloc + 1];
                *(float2*)(op + nloc) = v;
            }
        }
    }
}

// ---------------- launch ------------------------------------------------------------
extern "C" void kernel_launch(void* const* d_in, const int* in_sizes, int n_in,
                              void* d_out, int out_size) {
    const float*         x    = (const float*)d_in[0];
    const unsigned char* mask = (const unsigned char*)d_in[1];
    const int*           tl   = (const int*)d_in[2];
    const float*         W    = (const float*)d_in[3];
    const float*         bias = (const float*)d_in[4];
    float*               out  = (float*)d_out;

    float* asum_out = out + (size_t)TMAX * BB * CC;

    cudaFuncSetAttribute(gemm_kernel, cudaFuncAttributeMaxDynamicSharedMemorySize, SMEM_GEMM);

    sigmoid_kernel<<<(BB * SS) / 256, 256>>>(x, mask);
    scan_kernel<<<BB, 512>>>(tl, asum_out);
    prep_w_kernel<<<(512 * 512 + 255) / 256, 256>>>(W);
    gather_kernel<<<BB * 128, 256>>>(x);
    gemm_kernel<<<dim3(8192 / GBM, 512 / GBN), 256, SMEM_GEMM>>>(bias, tl, out);
}

// round 13
// speedup vs baseline: 1.2870x; 1.0155x over previous
#include <cuda_runtime.h>
#include <cuda_fp16.h>
#include <math.h>
#include <stdint.h>

// Problem constants
#define SS   4096
#define BB   16
#define CC   512
#define TMAX 512
#define INVN (TMAX + 2)   // 514

// ---------------- device scratch (static; no cudaMalloc) ----------------------------
__device__ float g_sig  [BB * SS];          // raw sigmoid
__device__ float g_alpha[BB * SS];          // scaled alpha
__device__ float g_csum [BB * SS];
__device__ int   g_f    [BB * SS];
__device__ int   g_inv  [BB * INVN];        // inv[t] = first s with f[s] >= t
__device__ __align__(16) __half g_Ah[8192 * 512];
__device__ __align__(16) __half g_Al[8192 * 512];
__device__ __align__(16) __half g_Bh[512 * 512];

__constant__ int c_off[13] = {0,4096,6144,7168,7680,7936,8064,8128,8160,8176,8184,8188,8190};

__device__ __forceinline__ uint32_t sm32(const void* p) {
    uint32_t a;
    asm("{ .reg .u64 t; cvta.to.shared.u64 t, %1; cvt.u32.u64 %0, t; }" : "=r"(a) : "l"(p));
    return a;
}
__device__ __forceinline__ void cpa16(uint32_t dst, const void* src) {
    asm volatile("cp.async.cg.shared.global [%0], [%1], 16;" :: "r"(dst), "l"(src) : "memory");
}

// ---------------- Phase 1a: fp64 sigmoid spread over the whole chip -----------------
__global__ __launch_bounds__(256)
void sigmoid_kernel(const float* __restrict__ x, const unsigned char* __restrict__ mask) {
    int i = blockIdx.x * 256 + threadIdx.x;    // i = b*SS + s
    int b = i >> 12;
    int s = i & (SS - 1);
    float a = mask[i] ? -10000.0f : x[(size_t)s * (BB*CC) + b * CC + (CC - 1)];
    double sg = 1.0 / (1.0 + exp(-(double)a));
    g_sig[i] = (float)sg;
}

// ---------------- Phase 1b: fp32 reduce + exact JAX-tree cumsum + fire + inv map ----
__device__ __forceinline__ void downsweep(float* sb, int tid) {
    for (int l = 1; l <= 12; l++) {
        int sz = SS >> l;
        int o  = c_off[l], oi = c_off[l-1];
        for (int i = tid; i < sz; i += 512)
            sb[o + i] = sb[oi + 2*i] + sb[oi + 2*i + 1];
        __syncthreads();
    }
}
__device__ __forceinline__ void upsweep(float* sb, int tid) {
    for (int l = 11; l >= 0; l--) {
        int sz = SS >> l;
        int o  = c_off[l], ou = c_off[l+1];
        for (int i = tid; i < sz; i += 512) {
            float v;
            if (i & 1)          v = sb[ou + (i >> 1)];
            else if (i == 0)    v = sb[o];
            else                v = sb[ou + (i >> 1) - 1] + sb[o + i];
            sb[o + i] = v;
        }
        __syncthreads();
    }
}

__global__ __launch_bounds__(512)
void scan_kernel(const int* __restrict__ tl, float* __restrict__ alpha_sum_out) {
    __shared__ float sb[8192];
    int b   = blockIdx.x;
    int tid = threadIdx.x;

    for (int s = tid; s < SS; s += 512) sb[s] = g_sig[b * SS + s];
    __syncthreads();

    downsweep(sb, tid);
    float asum = sb[c_off[12]];
    if (tid == 0) alpha_sum_out[b] = asum;
    float tlf = (float)tl[b];
    __syncthreads();

    for (int s = tid; s < SS; s += 512) {
        float sc = (sb[s] * tlf) / asum;
        sb[s] = sc;
        g_alpha[b * SS + s] = sc;
    }
    __syncthreads();

    downsweep(sb, tid);
    upsweep(sb, tid);

    for (int s = tid; s < SS; s += 512) {
        float c = sb[s];
        g_csum[b * SS + s] = c;
        g_f  [b * SS + s] = (int)floorf(c + 1e-4f);
    }

    // ---- build inverse map: inv[t] = first s with f[s] >= t ----
    for (int i = tid; i < INVN; i += 512)
        g_inv[b * INVN + i] = (i == 0) ? 0 : SS;
    __syncthreads();
    for (int s = tid; s < SS; s += 512) {
        int d1 = (int)floorf(sb[s] + 1e-4f);
        int d0 = (s == 0) ? 0 : (int)floorf(sb[s - 1] + 1e-4f);
        int te = d1 < (INVN - 1) ? d1 : (INVN - 1);
        for (int t = d0 + 1; t <= te; t++)
            g_inv[b * INVN + t] = s;     // disjoint ranges: no race
    }
}

// ---------------- Phase 1c: W -> fp16, row-major [n][k] -----------------------------
__global__ void prep_w_kernel(const float* __restrict__ W) {
    int i = blockIdx.x * 256 + threadIdx.x;
    if (i >= 512 * 512) return;
    int n = i >> 9;
    int k = i & 511;
    float v = (k < 511) ? W[n * 511 + k] : 0.0f;
    g_Bh[i] = __float2half(v);
}

// ---------------- Phase 2: gather, TT=4, per-thread cp.async ring -------------------
#define TT 4
#define NSLOT 4   // per-thread 4 x 16B ring slots

__global__ __launch_bounds__(256)
void gather_kernel(const float* __restrict__ x) {
    int blk = blockIdx.x;              // b * 128 + tg
    int b   = blk >> 7;
    int tg  = blk & 127;
    int t0  = tg * TT;
    const int*   f  = g_f     + b * SS;
    const float* al = g_alpha + b * SS;
    const float* cs = g_csum  + b * SS;
    const int*   iv = g_inv   + b * INVN;

    // O(1) window from inverse map
    int lo  = (t0 == 0) ? 0 : iv[t0 - 1];
    int hiv = iv[t0 + TT];
    int hi  = (hiv < SS - 1) ? hiv : SS - 1;

    __shared__ float4 ring[NSLOT * 256];   // [slot][tid] -> 16 KB; reused as red buffer
    __shared__ float4 wbuf[144];           // [row] -> weights for 4 t's; pad zeroed

    int tid  = threadIdx.x;
    int half = tid >> 7;                   // 0: even rows, 1: odd rows
    int l128 = tid & 127;
    int c0   = l128 * 4;                   // channels c0..c0+3
    uint32_t ringb = sm32(ring) + (uint32_t)tid * 16;

    float4 acc[TT];
    #pragma unroll
    for (int tt = 0; tt < TT; tt++) acc[tt] = make_float4(0.f, 0.f, 0.f, 0.f);

    if (tid >= 128 && tid < 144) wbuf[tid] = make_float4(0.f, 0.f, 0.f, 0.f);

    for (int base = lo; base <= hi; base += 128) {
        // all pending cp.async must land before ring slots are reused
        asm volatile("cp.async.wait_group 0;" ::: "memory");
        if (tid < 128) {
            int s = base + tid;
            float4 wv = make_float4(0.f, 0.f, 0.f, 0.f);
            if (s <= hi) {
                int   d1   = f[s];
                int   d0   = (s == 0) ? 0 : f[s - 1];
                int   fire = d1 - d0;
                float a    = al[s];
                float c    = cs[s];
                float ex   = (fire > 1) ? (float)(fire - 1) : 0.f;
                float rw   = (fire > 0) ? (c - (float)d1) : a;
                float lw   = (a - rw) - ex;
                int   ei   = d0 + 1; if (ei > TMAX - 1) ei = TMAX - 1;
                float exc  = fminf(ex, 1.0f);
                float w[TT];
                #pragma unroll
                for (int tt = 0; tt < TT; tt++) {
                    int t = t0 + tt;
                    float ww = 0.f;
                    if (d1 == t) ww += rw;
                    if (d0 == t) ww += lw;
                    if (ei == t) ww += exc;
                    if (t >= d0 + 2 && t < d1) ww = 1.0f;   // fill overwrite
                    w[tt] = ww;
                }
                wv = make_float4(w[0], w[1], w[2], w[3]);
            }
            wbuf[tid] = wv;
        }
        __syncthreads();

        int n = hi - base + 1; if (n > 128) n = 128;
        const float* xp = x + (size_t)base * (BB*CC) + b * CC + c0;
        int ih = (n - half + 1) >> 1;      // rows of my parity in this chunk

        // prologue: fill the ring (clamped rows carry zero weight)
        #pragma unroll
        for (int i = 0; i < NSLOT; i++) {
            int r = 2*i + half; r = r < n ? r : n - 1;
            cpa16(ringb + (uint32_t)(i * 256) * 16, xp + (size_t)r * (BB*CC));
            asm volatile("cp.async.commit_group;" ::: "memory");
        }
        for (int i = 0; i < ih; i++) {
            asm volatile("cp.async.wait_group %0;" :: "n"(NSLOT - 1) : "memory");
            int slot = i & (NSLOT - 1);
            float4 v = ring[slot * 256 + tid];
            // refill this slot immediately (write lands >= L2 latency after LDS read)
            int r = 2*(i + NSLOT) + half; r = r < n ? r : n - 1;
            cpa16(ringb + (uint32_t)(slot * 256) * 16, xp + (size_t)r * (BB*CC));
            asm volatile("cp.async.commit_group;" ::: "memory");

            float4 wq = wbuf[2*i + half];
            acc[0].x += wq.x * v.x; acc[0].y += wq.x * v.y;
            acc[0].z += wq.x * v.z; acc[0].w += wq.x * v.w;
            acc[1].x += wq.y * v.x; acc[1].y += wq.y * v.y;
            acc[1].z += wq.y * v.z; acc[1].w += wq.y * v.w;
            acc[2].x += wq.z * v.x; acc[2].y += wq.z * v.y;
            acc[2].z += wq.z * v.z; acc[2].w += wq.z * v.w;
            acc[3].x += wq.w * v.x; acc[3].y += wq.w * v.y;
            acc[3].z += wq.w * v.z; acc[3].w += wq.w * v.w;
        }
        __syncthreads();   // wbuf stable until all threads finish the chunk
    }

    // drain outstanding copies, then reuse ring as the even/odd reduction buffer
    asm volatile("cp.async.wait_group 0;" ::: "memory");
    __syncthreads();
    if (half == 1) {
        #pragma unroll
        for (int tt = 0; tt < TT; tt++) ring[tt * 128 + l128] = acc[tt];
    }
    __syncthreads();
    if (half == 0) {
        #pragma unroll
        for (int tt = 0; tt < TT; tt++) {
            float4 o = ring[tt * 128 + l128];
            float4 a = acc[tt];
            a.x += o.x; a.y += o.y; a.z += o.z; a.w += o.w;
            if (l128 == 127) a.w = 0.f;   // channel 511 excluded
            __half h0 = __float2half(a.x), h1 = __float2half(a.y);
            __half h2 = __float2half(a.z), h3 = __float2half(a.w);
            __half l0 = __float2half(a.x - __half2float(h0));
            __half l1 = __float2half(a.y - __half2float(h1));
            __half l2 = __float2half(a.z - __half2float(h2));
            __half l3 = __float2half(a.w - __half2float(h3));
            uint2 uh, ul;
            uh.x = (uint32_t)__half_as_ushort(h0) | ((uint32_t)__half_as_ushort(h1) << 16);
            uh.y = (uint32_t)__half_as_ushort(h2) | ((uint32_t)__half_as_ushort(h3) << 16);
            ul.x = (uint32_t)__half_as_ushort(l0) | ((uint32_t)__half_as_ushort(l1) << 16);
            ul.y = (uint32_t)__half_as_ushort(l2) | ((uint32_t)__half_as_ushort(l3) << 16);
            size_t o2 = (size_t)(b * 512 + t0 + tt) * 512 + c0;
            *(uint2*)&g_Ah[o2] = uh;
            *(uint2*)&g_Al[o2] = ul;
        }
    }
}

// ---------------- Phase 3: fp16 2-product GEMM, 3-stage cp.async, 1 sync/chunk ------
#define GBM 128
#define GBN 128
#define GBK 32
#define AST 40
#define BUF_ELEMS (128 * AST)
#define NBUF 3                                   // Ah, Al, Bh
#define SMEM_GEMM (3 * NBUF * BUF_ELEMS * 2)     // 3 stages = 92160

__device__ __forceinline__ void ldsm4(uint32_t* r, uint32_t addr) {
    asm volatile("ldmatrix.sync.aligned.m8n8.x4.shared.b16 {%0,%1,%2,%3}, [%4];"
        : "=r"(r[0]), "=r"(r[1]), "=r"(r[2]), "=r"(r[3]) : "r"(addr));
}
__device__ __forceinline__ void mma16816(float* c, const uint32_t* a, const uint32_t* b) {
    asm volatile("mma.sync.aligned.m16n8k16.row.col.f32.f16.f16.f32 "
        "{%0,%1,%2,%3}, {%4,%5,%6,%7}, {%8,%9}, {%0,%1,%2,%3};"
        : "+f"(c[0]), "+f"(c[1]), "+f"(c[2]), "+f"(c[3])
        : "r"(a[0]), "r"(a[1]), "r"(a[2]), "r"(a[3]), "r"(b[0]), "r"(b[1]));
}

extern __shared__ __align__(16) __half dsm[];

__global__ __launch_bounds__(256, 2)
void gemm_kernel(const float* __restrict__ bias, const int* __restrict__ tl,
                 float* __restrict__ out) {
    int tid  = threadIdx.x;
    int wid  = tid >> 5, lane = tid & 31;
    int wm   = wid & 1,  wn   = wid >> 1;       // warp grid 2 x 4
    int bm   = blockIdx.x * GBM;
    int bn   = blockIdx.y * GBN;
    int lq   = lane >> 2;
    int lr   = lane & 3;

    // all-zero M-block skip: rows t > tl[b] have zero feats -> out = bias
    {
        int bb  = bm >> 9;
        int t0b = bm & 511;
        if (t0b > tl[bb]) {
            int rowi = tid >> 1;
            int cq   = (tid & 1) * 64;
            int t    = t0b + rowi;
            float* op = out + (size_t)t * (BB * CC) + bb * CC + bn + cq;
            const float* bp = bias + bn + cq;
            #pragma unroll
            for (int j = 0; j < 64; j += 4)
                *(float4*)(op + j) = *(const float4*)(bp + j);
            return;
        }
    }

    int crow = tid >> 1;
    int ckq  = (tid & 1) * 16;

    uint32_t smb = sm32(dsm);

    int arow = (lane & 7) + ((lane >> 3) & 1) * 8;   // A: row within 16
    int akc  = (lane >> 4) * 8;                      // A: k offset 0/8
    int bnof = (lane >> 4) * 8 + (lane & 7);         // B: n within 16
    int bkc  = ((lane >> 3) & 1) * 8;                // B: k offset 0/8

    float acc[4][4][4];
    #pragma unroll
    for (int mi = 0; mi < 4; mi++)
        #pragma unroll
        for (int ni = 0; ni < 4; ni++)
            #pragma unroll
            for (int q = 0; q < 4; q++) acc[mi][ni][q] = 0.f;

    const __half* gA  = g_Ah + (size_t)(bm + crow) * 512 + ckq;
    const __half* gAl = g_Al + (size_t)(bm + crow) * 512 + ckq;
    const __half* gB  = g_Bh + (size_t)(bn + crow) * 512 + ckq;

    #define ISSUE_STAGE(c, st) do {                                                   \
        int k0 = (c) * GBK;                                                           \
        uint32_t dbase = smb + (uint32_t)((((st)*NBUF)*128 + crow)*AST + ckq) * 2;     \
        cpa16(dbase,                      gA  + k0);                                   \
        cpa16(dbase + 16,                 gA  + k0 + 8);                               \
        cpa16(dbase + BUF_ELEMS*2,        gAl + k0);                                   \
        cpa16(dbase + BUF_ELEMS*2 + 16,   gAl + k0 + 8);                               \
        cpa16(dbase + 2*BUF_ELEMS*2,      gB  + k0);                                   \
        cpa16(dbase + 2*BUF_ELEMS*2 + 16, gB  + k0 + 8);                               \
    } while (0)

    ISSUE_STAGE(0, 0);
    asm volatile("cp.async.commit_group;" ::: "memory");
    ISSUE_STAGE(1, 1);
    asm volatile("cp.async.commit_group;" ::: "memory");

    for (int c = 0; c < 16; c++) {
        int st = c % 3;
        asm volatile("cp.async.wait_group 1;" ::: "memory");
        __syncthreads();   // stage c ready; everyone done reading stage (c+2)%3

        uint32_t sAh = smb + (uint32_t)((st*NBUF + 0) * BUF_ELEMS) * 2;
        uint32_t sAl = smb + (uint32_t)((st*NBUF + 1) * BUF_ELEMS) * 2;
        uint32_t sBh = smb + (uint32_t)((st*NBUF + 2) * BUF_ELEMS) * 2;

        #pragma unroll
        for (int ks = 0; ks < 2; ks++) {
            int kb = ks * 16;
            uint32_t bh[4][2];
            #pragma unroll
            for (int nip = 0; nip < 2; nip++) {
                int ncol = wn * 32 + nip * 16 + bnof;
                uint32_t off = (uint32_t)(ncol * AST + kb + bkc) * 2;
                uint32_t r[4];
                ldsm4(r, sBh + off);
                bh[nip*2+0][0] = r[0]; bh[nip*2+0][1] = r[1];
                bh[nip*2+1][0] = r[2]; bh[nip*2+1][1] = r[3];
            }
            #pragma unroll
            for (int mi = 0; mi < 4; mi++) {
                int row = wm * 64 + mi * 16 + arow;
                uint32_t off = (uint32_t)(row * AST + kb + akc) * 2;
                uint32_t a[4];
                ldsm4(a, sAh + off);
                #pragma unroll
                for (int ni = 0; ni < 4; ni++) mma16816(acc[mi][ni], a, bh[ni]);
                ldsm4(a, sAl + off);
                #pragma unroll
                for (int ni = 0; ni < 4; ni++) mma16816(acc[mi][ni], a, bh[ni]);
            }
        }

        if (c + 2 < 16) ISSUE_STAGE(c + 2, (c + 2) % 3);
        asm volatile("cp.async.commit_group;" ::: "memory");
    }

    // epilogue: out layout (T, B, C): idx = t*(B*C) + b*C + n, with m = b*512 + t
    #pragma unroll
    for (int mi = 0; mi < 4; mi++) {
        int mrow = bm + wm * 64 + mi * 16 + lq;
        #pragma unroll
        for (int half = 0; half < 2; half++) {
            int m = mrow + half * 8;
            int b = m >> 9;
            int t = m & 511;
            float* op = out + (size_t)t * (BB * CC) + b * CC + bn;
            #pragma unroll
            for (int ni = 0; ni < 4; ni++) {
                int nloc = wn * 32 + ni * 8 + lr * 2;
                float2 v;
                v.x = acc[mi][ni][half * 2 + 0] + bias[bn + nloc];
                v.y = acc[mi][ni][half * 2 + 1] + bias[bn + nloc + 1];
                *(float2*)(op + nloc) = v;
            }
        }
    }
}

// ---------------- launch ------------------------------------------------------------
extern "C" void kernel_launch(void* const* d_in, const int* in_sizes, int n_in,
                              void* d_out, int out_size) {
    const float*         x    = (const float*)d_in[0];
    const unsigned char* mask = (const unsigned char*)d_in[1];
    const int*           tl   = (const int*)d_in[2];
    const float*         W    = (const float*)d_in[3];
    const float*         bias = (const float*)d_in[4];
    float*               out  = (float*)d_out;

    float* asum_out = out + (size_t)TMAX * BB * CC;

    cudaFuncSetAttribute(gemm_kernel, cudaFuncAttributeMaxDynamicSharedMemorySize, SMEM_GEMM);

    sigmoid_kernel<<<(BB * SS) / 256, 256>>>(x, mask);
    scan_kernel<<<BB, 512>>>(tl, asum_out);
    prep_w_kernel<<<(512 * 512 + 255) / 256, 256>>>(W);
    gather_kernel<<<BB * 128, 256>>>(x);
    gemm_kernel<<<dim3(8192 / GBM, 512 / GBN), 256, SMEM_GEMM>>>(bias, tl, out);
}

// round 14
// speedup vs baseline: 1.3221x; 1.0273x over previous
#include <cuda_runtime.h>
#include <cuda_fp16.h>
#include <math.h>
#include <stdint.h>

// Problem constants
#define SS   4096
#define BB   16
#define CC   512
#define TMAX 512
#define INVN (TMAX + 2)   // 514

// ---------------- device scratch (static; no cudaMalloc) ----------------------------
__device__ float g_sig  [BB * SS];          // raw sigmoid
__device__ float g_alpha[BB * SS];          // scaled alpha
__device__ float g_csum [BB * SS];
__device__ int   g_f    [BB * SS];
__device__ int   g_inv  [BB * INVN];        // inv[t] = first s with f[s] >= t
__device__ __align__(16) __half g_Ah[8192 * 512];
__device__ __align__(16) __half g_Al[8192 * 512];
__device__ __align__(16) __half g_Bh[512 * 512];

__constant__ int c_off[13] = {0,4096,6144,7168,7680,7936,8064,8128,8160,8176,8184,8188,8190};

__device__ __forceinline__ uint32_t sm32(const void* p) {
    uint32_t a;
    asm("{ .reg .u64 t; cvta.to.shared.u64 t, %1; cvt.u32.u64 %0, t; }" : "=r"(a) : "l"(p));
    return a;
}
__device__ __forceinline__ void cpa16(uint32_t dst, const void* src) {
    asm volatile("cp.async.cg.shared.global [%0], [%1], 16;" :: "r"(dst), "l"(src) : "memory");
}

// ---------------- Phase 1a: fp64 sigmoid (blocks 0..255) + W->fp16 (blocks 256..1279)
__global__ __launch_bounds__(256)
void misc_kernel(const float* __restrict__ x, const unsigned char* __restrict__ mask,
                 const float* __restrict__ W) {
    int bid = blockIdx.x;
    if (bid < 256) {
        int i = bid * 256 + threadIdx.x;           // i = b*SS + s
        int b = i >> 12;
        int s = i & (SS - 1);
        float a = mask[i] ? -10000.0f : x[(size_t)s * (BB*CC) + b * CC + (CC - 1)];
        double sg = 1.0 / (1.0 + exp(-(double)a));
        g_sig[i] = (float)sg;
    } else {
        int i = (bid - 256) * 256 + threadIdx.x;   // i = n*512 + k
        if (i < 512 * 512) {
            int n = i >> 9;
            int k = i & 511;
            float v = (k < 511) ? W[n * 511 + k] : 0.0f;
            g_Bh[i] = __float2half(v);
        }
    }
}

// ---------------- Phase 1b: fp32 reduce + exact JAX-tree cumsum + fire + inv map ----
__device__ __forceinline__ void downsweep(float* sb, int tid) {
    for (int l = 1; l <= 12; l++) {
        int sz = SS >> l;
        int o  = c_off[l], oi = c_off[l-1];
        for (int i = tid; i < sz; i += 512)
            sb[o + i] = sb[oi + 2*i] + sb[oi + 2*i + 1];
        __syncthreads();
    }
}
__device__ __forceinline__ void upsweep(float* sb, int tid) {
    for (int l = 11; l >= 0; l--) {
        int sz = SS >> l;
        int o  = c_off[l], ou = c_off[l+1];
        for (int i = tid; i < sz; i += 512) {
            float v;
            if (i & 1)          v = sb[ou + (i >> 1)];
            else if (i == 0)    v = sb[o];
            else                v = sb[ou + (i >> 1) - 1] + sb[o + i];
            sb[o + i] = v;
        }
        __syncthreads();
    }
}

__global__ __launch_bounds__(512)
void scan_kernel(const int* __restrict__ tl, float* __restrict__ alpha_sum_out) {
    __shared__ float sb[8192];
    int b   = blockIdx.x;
    int tid = threadIdx.x;

    for (int s = tid; s < SS; s += 512) sb[s] = g_sig[b * SS + s];
    __syncthreads();

    downsweep(sb, tid);
    float asum = sb[c_off[12]];
    if (tid == 0) alpha_sum_out[b] = asum;
    float tlf = (float)tl[b];
    __syncthreads();

    for (int s = tid; s < SS; s += 512) {
        float sc = (sb[s] * tlf) / asum;
        sb[s] = sc;
        g_alpha[b * SS + s] = sc;
    }
    __syncthreads();

    downsweep(sb, tid);
    upsweep(sb, tid);

    for (int s = tid; s < SS; s += 512) {
        float c = sb[s];
        g_csum[b * SS + s] = c;
        g_f  [b * SS + s] = (int)floorf(c + 1e-4f);
    }

    // ---- build inverse map: inv[t] = first s with f[s] >= t ----
    for (int i = tid; i < INVN; i += 512)
        g_inv[b * INVN + i] = (i == 0) ? 0 : SS;
    __syncthreads();
    for (int s = tid; s < SS; s += 512) {
        int d1 = (int)floorf(sb[s] + 1e-4f);
        int d0 = (s == 0) ? 0 : (int)floorf(sb[s - 1] + 1e-4f);
        int te = d1 < (INVN - 1) ? d1 : (INVN - 1);
        for (int t = d0 + 1; t <= te; t++)
            g_inv[b * INVN + t] = s;     // disjoint ranges: no race
    }
}

// ---------------- Phase 2: gather, TT=4, per-thread cp.async ring -------------------
#define TT 4
#define NSLOT 4   // per-thread 4 x 16B ring slots

__global__ __launch_bounds__(256)
void gather_kernel(const float* __restrict__ x) {
    int blk = blockIdx.x;              // b * 128 + tg
    int b   = blk >> 7;
    int tg  = blk & 127;
    int t0  = tg * TT;
    const int*   f  = g_f     + b * SS;
    const float* al = g_alpha + b * SS;
    const float* cs = g_csum  + b * SS;
    const int*   iv = g_inv   + b * INVN;

    // O(1) window from inverse map
    int lo  = (t0 == 0) ? 0 : iv[t0 - 1];
    int hiv = iv[t0 + TT];
    int hi  = (hiv < SS - 1) ? hiv : SS - 1;

    __shared__ float4 ring[NSLOT * 256];   // [slot][tid] -> 16 KB; reused as red buffer
    __shared__ float4 wbuf[144];           // [row] -> weights for 4 t's; pad zeroed

    int tid  = threadIdx.x;
    int half = tid >> 7;                   // 0: even rows, 1: odd rows
    int l128 = tid & 127;
    int c0   = l128 * 4;                   // channels c0..c0+3
    uint32_t ringb = sm32(ring) + (uint32_t)tid * 16;

    float4 acc[TT];
    #pragma unroll
    for (int tt = 0; tt < TT; tt++) acc[tt] = make_float4(0.f, 0.f, 0.f, 0.f);

    if (tid >= 128 && tid < 144) wbuf[tid] = make_float4(0.f, 0.f, 0.f, 0.f);

    for (int base = lo; base <= hi; base += 128) {
        asm volatile("cp.async.wait_group 0;" ::: "memory");
        if (tid < 128) {
            int s = base + tid;
            float4 wv = make_float4(0.f, 0.f, 0.f, 0.f);
            if (s <= hi) {
                int   d1   = f[s];
                int   d0   = (s == 0) ? 0 : f[s - 1];
                int   fire = d1 - d0;
                float a    = al[s];
                float c    = cs[s];
                float ex   = (fire > 1) ? (float)(fire - 1) : 0.f;
                float rw   = (fire > 0) ? (c - (float)d1) : a;
                float lw   = (a - rw) - ex;
                int   ei   = d0 + 1; if (ei > TMAX - 1) ei = TMAX - 1;
                float exc  = fminf(ex, 1.0f);
                float w[TT];
                #pragma unroll
                for (int tt = 0; tt < TT; tt++) {
                    int t = t0 + tt;
                    float ww = 0.f;
                    if (d1 == t) ww += rw;
                    if (d0 == t) ww += lw;
                    if (ei == t) ww += exc;
                    if (t >= d0 + 2 && t < d1) ww = 1.0f;   // fill overwrite
                    w[tt] = ww;
                }
                wv = make_float4(w[0], w[1], w[2], w[3]);
            }
            wbuf[tid] = wv;
        }
        __syncthreads();

        int n = hi - base + 1; if (n > 128) n = 128;
        const float* xp = x + (size_t)base * (BB*CC) + b * CC + c0;
        int ih = (n - half + 1) >> 1;      // rows of my parity in this chunk

        #pragma unroll
        for (int i = 0; i < NSLOT; i++) {
            int r = 2*i + half; r = r < n ? r : n - 1;
            cpa16(ringb + (uint32_t)(i * 256) * 16, xp + (size_t)r * (BB*CC));
            asm volatile("cp.async.commit_group;" ::: "memory");
        }
        for (int i = 0; i < ih; i++) {
            asm volatile("cp.async.wait_group %0;" :: "n"(NSLOT - 1) : "memory");
            int slot = i & (NSLOT - 1);
            float4 v = ring[slot * 256 + tid];
            int r = 2*(i + NSLOT) + half; r = r < n ? r : n - 1;
            cpa16(ringb + (uint32_t)(slot * 256) * 16, xp + (size_t)r * (BB*CC));
            asm volatile("cp.async.commit_group;" ::: "memory");

            float4 wq = wbuf[2*i + half];
            acc[0].x += wq.x * v.x; acc[0].y += wq.x * v.y;
            acc[0].z += wq.x * v.z; acc[0].w += wq.x * v.w;
            acc[1].x += wq.y * v.x; acc[1].y += wq.y * v.y;
            acc[1].z += wq.y * v.z; acc[1].w += wq.y * v.w;
            acc[2].x += wq.z * v.x; acc[2].y += wq.z * v.y;
            acc[2].z += wq.z * v.z; acc[2].w += wq.z * v.w;
            acc[3].x += wq.w * v.x; acc[3].y += wq.w * v.y;
            acc[3].z += wq.w * v.z; acc[3].w += wq.w * v.w;
        }
        __syncthreads();
    }

    asm volatile("cp.async.wait_group 0;" ::: "memory");
    __syncthreads();
    if (half == 1) {
        #pragma unroll
        for (int tt = 0; tt < TT; tt++) ring[tt * 128 + l128] = acc[tt];
    }
    __syncthreads();
    if (half == 0) {
        #pragma unroll
        for (int tt = 0; tt < TT; tt++) {
            float4 o = ring[tt * 128 + l128];
            float4 a = acc[tt];
            a.x += o.x; a.y += o.y; a.z += o.z; a.w += o.w;
            if (l128 == 127) a.w = 0.f;   // channel 511 excluded
            __half h0 = __float2half(a.x), h1 = __float2half(a.y);
            __half h2 = __float2half(a.z), h3 = __float2half(a.w);
            __half l0 = __float2half(a.x - __half2float(h0));
            __half l1 = __float2half(a.y - __half2float(h1));
            __half l2 = __float2half(a.z - __half2float(h2));
            __half l3 = __float2half(a.w - __half2float(h3));
            uint2 uh, ul;
            uh.x = (uint32_t)__half_as_ushort(h0) | ((uint32_t)__half_as_ushort(h1) << 16);
            uh.y = (uint32_t)__half_as_ushort(h2) | ((uint32_t)__half_as_ushort(h3) << 16);
            ul.x = (uint32_t)__half_as_ushort(l0) | ((uint32_t)__half_as_ushort(l1) << 16);
            ul.y = (uint32_t)__half_as_ushort(l2) | ((uint32_t)__half_as_ushort(l3) << 16);
            size_t o2 = (size_t)(b * 512 + t0 + tt) * 512 + c0;
            *(uint2*)&g_Ah[o2] = uh;
            *(uint2*)&g_Al[o2] = ul;
        }
    }
}

// ---------------- Phase 3: fp16 2-product GEMM, 3-stage cp.async, n-major grid ------
#define GBM 128
#define GBN 128
#define GBK 32
#define AST 40
#define BUF_ELEMS (128 * AST)
#define NBUF 3                                   // Ah, Al, Bh
#define SMEM_GEMM (3 * NBUF * BUF_ELEMS * 2)     // 3 stages = 92160

__device__ __forceinline__ void ldsm4(uint32_t* r, uint32_t addr) {
    asm volatile("ldmatrix.sync.aligned.m8n8.x4.shared.b16 {%0,%1,%2,%3}, [%4];"
        : "=r"(r[0]), "=r"(r[1]), "=r"(r[2]), "=r"(r[3]) : "r"(addr));
}
__device__ __forceinline__ void mma16816(float* c, const uint32_t* a, const uint32_t* b) {
    asm volatile("mma.sync.aligned.m16n8k16.row.col.f32.f16.f16.f32 "
        "{%0,%1,%2,%3}, {%4,%5,%6,%7}, {%8,%9}, {%0,%1,%2,%3};"
        : "+f"(c[0]), "+f"(c[1]), "+f"(c[2]), "+f"(c[3])
        : "r"(a[0]), "r"(a[1]), "r"(a[2]), "r"(a[3]), "r"(b[0]), "r"(b[1]));
}

extern __shared__ __align__(16) __half dsm[];

__global__ __launch_bounds__(256, 2)
void gemm_kernel(const float* __restrict__ bias, const int* __restrict__ tl,
                 float* __restrict__ out) {
    int tid  = threadIdx.x;
    int wid  = tid >> 5, lane = tid & 31;
    int wm   = wid & 1,  wn   = wid >> 1;       // warp grid 2 x 4
    // n-major grid: 4 n-blocks of the same m launch adjacently -> A tile L2 reuse
    int bm   = blockIdx.y * GBM;
    int bn   = blockIdx.x * GBN;
    int lq   = lane >> 2;
    int lr   = lane & 3;

    // all-zero M-block skip: rows t > tl[b] have zero feats -> out = bias
    {
        int bb  = bm >> 9;
        int t0b = bm & 511;
        if (t0b > tl[bb]) {
            int rowi = tid >> 1;
            int cq   = (tid & 1) * 64;
            int t    = t0b + rowi;
            float* op = out + (size_t)t * (BB * CC) + bb * CC + bn + cq;
            const float* bp = bias + bn + cq;
            #pragma unroll
            for (int j = 0; j < 64; j += 4)
                *(float4*)(op + j) = *(const float4*)(bp + j);
            return;
        }
    }

    int crow = tid >> 1;
    int ckq  = (tid & 1) * 16;

    uint32_t smb = sm32(dsm);

    int arow = (lane & 7) + ((lane >> 3) & 1) * 8;   // A: row within 16
    int akc  = (lane >> 4) * 8;                      // A: k offset 0/8
    int bnof = (lane >> 4) * 8 + (lane & 7);         // B: n within 16
    int bkc  = ((lane >> 3) & 1) * 8;                // B: k offset 0/8

    float acc[4][4][4];
    #pragma unroll
    for (int mi = 0; mi < 4; mi++)
        #pragma unroll
        for (int ni = 0; ni < 4; ni++)
            #pragma unroll
            for (int q = 0; q < 4; q++) acc[mi][ni][q] = 0.f;

    const __half* gA  = g_Ah + (size_t)(bm + crow) * 512 + ckq;
    const __half* gAl = g_Al + (size_t)(bm + crow) * 512 + ckq;
    const __half* gB  = g_Bh + (size_t)(bn + crow) * 512 + ckq;

    #define ISSUE_STAGE(c, st) do {                                                   \
        int k0 = (c) * GBK;                                                           \
        uint32_t dbase = smb + (uint32_t)((((st)*NBUF)*128 + crow)*AST + ckq) * 2;     \
        cpa16(dbase,                      gA  + k0);                                   \
        cpa16(dbase + 16,                 gA  + k0 + 8);                               \
        cpa16(dbase + BUF_ELEMS*2,        gAl + k0);                                   \
        cpa16(dbase + BUF_ELEMS*2 + 16,   gAl + k0 + 8);                               \
        cpa16(dbase + 2*BUF_ELEMS*2,      gB  + k0);                                   \
        cpa16(dbase + 2*BUF_ELEMS*2 + 16, gB  + k0 + 8);                               \
    } while (0)

    ISSUE_STAGE(0, 0);
    asm volatile("cp.async.commit_group;" ::: "memory");
    ISSUE_STAGE(1, 1);
    asm volatile("cp.async.commit_group;" ::: "memory");

    for (int c = 0; c < 16; c++) {
        int st = c % 3;
        asm volatile("cp.async.wait_group 1;" ::: "memory");
        __syncthreads();   // stage c ready; everyone done reading stage (c+2)%3

        uint32_t sAh = smb + (uint32_t)((st*NBUF + 0) * BUF_ELEMS) * 2;
        uint32_t sAl = smb + (uint32_t)((st*NBUF + 1) * BUF_ELEMS) * 2;
        uint32_t sBh = smb + (uint32_t)((st*NBUF + 2) * BUF_ELEMS) * 2;

        #pragma unroll
        for (int ks = 0; ks < 2; ks++) {
            int kb = ks * 16;
            uint32_t bh[4][2];
            #pragma unroll
            for (int nip = 0; nip < 2; nip++) {
                int ncol = wn * 32 + nip * 16 + bnof;
                uint32_t off = (uint32_t)(ncol * AST + kb + bkc) * 2;
                uint32_t r[4];
                ldsm4(r, sBh + off);
                bh[nip*2+0][0] = r[0]; bh[nip*2+0][1] = r[1];
                bh[nip*2+1][0] = r[2]; bh[nip*2+1][1] = r[3];
            }
            #pragma unroll
            for (int mi = 0; mi < 4; mi++) {
                int row = wm * 64 + mi * 16 + arow;
                uint32_t off = (uint32_t)(row * AST + kb + akc) * 2;
                uint32_t a[4];
                ldsm4(a, sAh + off);
                #pragma unroll
                for (int ni = 0; ni < 4; ni++) mma16816(acc[mi][ni], a, bh[ni]);
                ldsm4(a, sAl + off);
                #pragma unroll
                for (int ni = 0; ni < 4; ni++) mma16816(acc[mi][ni], a, bh[ni]);
            }
        }

        if (c + 2 < 16) ISSUE_STAGE(c + 2, (c + 2) % 3);
        asm volatile("cp.async.commit_group;" ::: "memory");
    }

    // epilogue: out layout (T, B, C): idx = t*(B*C) + b*C + n, with m = b*512 + t
    #pragma unroll
    for (int mi = 0; mi < 4; mi++) {
        int mrow = bm + wm * 64 + mi * 16 + lq;
        #pragma unroll
        for (int half = 0; half < 2; half++) {
            int m = mrow + half * 8;
            int b = m >> 9;
            int t = m & 511;
            float* op = out + (size_t)t * (BB * CC) + b * CC + bn;
            #pragma unroll
            for (int ni = 0; ni < 4; ni++) {
                int nloc = wn * 32 + ni * 8 + lr * 2;
                float2 v;
                v.x = acc[mi][ni][half * 2 + 0] + bias[bn + nloc];
                v.y = acc[mi][ni][half * 2 + 1] + bias[bn + nloc + 1];
                *(float2*)(op + nloc) = v;
            }
        }
    }
}

// ---------------- launch ------------------------------------------------------------
extern "C" void kernel_launch(void* const* d_in, const int* in_sizes, int n_in,
                              void* d_out, int out_size) {
    const float*         x    = (const float*)d_in[0];
    const unsigned char* mask = (const unsigned char*)d_in[1];
    const int*           tl   = (const int*)d_in[2];
    const float*         W    = (const float*)d_in[3];
    const float*         bias = (const float*)d_in[4];
    float*               out  = (float*)d_out;

    float* asum_out = out + (size_t)TMAX * BB * CC;

    cudaFuncSetAttribute(gemm_kernel, cudaFuncAttributeMaxDynamicSharedMemorySize, SMEM_GEMM);

    misc_kernel<<<256 + 1024, 256>>>(x, mask, W);
    scan_kernel<<<BB, 512>>>(tl, asum_out);
    gather_kernel<<<BB * 128, 256>>>(x);
    gemm_kernel<<<dim3(512 / GBN, 8192 / GBM), 256, SMEM_GEMM>>>(bias, tl, out);
}

// round 16
// speedup vs baseline: 1.4252x; 1.0780x over previous
#include <cuda_runtime.h>
#include <cuda_fp16.h>
#include <math.h>
#include <stdint.h>

// Problem constants
#define SS   4096
#define BB   16
#define CC   512
#define TMAX 512
#define INVN (TMAX + 2)   // 514

// ---------------- device scratch (static; no cudaMalloc) ----------------------------
__device__ float g_sig  [BB * SS];          // raw sigmoid
__device__ float g_alpha[BB * SS];          // scaled alpha
__device__ float g_csum [BB * SS];
__device__ int   g_f    [BB * SS];
__device__ int   g_inv  [BB * INVN];        // inv[t] = first s with f[s] >= t
__device__ __align__(16) __half g_Ah[8192 * 512];
__device__ __align__(16) __half g_Al[8192 * 512];
__device__ __align__(16) __half g_Bh[512 * 512];

__constant__ int c_off[13] = {0,4096,6144,7168,7680,7936,8064,8128,8160,8176,8184,8188,8190};

__device__ __forceinline__ uint32_t sm32(const void* p) {
    uint32_t a;
    asm("{ .reg .u64 t; cvta.to.shared.u64 t, %1; cvt.u32.u64 %0, t; }" : "=r"(a) : "l"(p));
    return a;
}
__device__ __forceinline__ void cpa16(uint32_t dst, const void* src) {
    asm volatile("cp.async.cg.shared.global [%0], [%1], 16;" :: "r"(dst), "l"(src) : "memory");
}

// ---------------- Phase 1a: fp64 sigmoid (blocks 0..255) + W->fp16 (blocks 256..1279)
__global__ __launch_bounds__(256)
void misc_kernel(const float* __restrict__ x, const unsigned char* __restrict__ mask,
                 const float* __restrict__ W) {
    int bid = blockIdx.x;
    if (bid < 256) {
        int i = bid * 256 + threadIdx.x;           // i = b*SS + s
        int b = i >> 12;
        int s = i & (SS - 1);
        float a = mask[i] ? -10000.0f : x[(size_t)s * (BB*CC) + b * CC + (CC - 1)];
        double sg = 1.0 / (1.0 + exp(-(double)a));
        g_sig[i] = (float)sg;
    } else {
        int i = (bid - 256) * 256 + threadIdx.x;   // i = n*512 + k
        if (i < 512 * 512) {
            int n = i >> 9;
            int k = i & 511;
            float v = (k < 511) ? W[n * 511 + k] : 0.0f;
            g_Bh[i] = __float2half(v);
        }
    }
}

// ---------------- Phase 1b: fp32 reduce + exact JAX-tree cumsum + fire + inv map ----
__device__ __forceinline__ void downsweep(float* sb, int tid) {
    for (int l = 1; l <= 12; l++) {
        int sz = SS >> l;
        int o  = c_off[l], oi = c_off[l-1];
        for (int i = tid; i < sz; i += 512)
            sb[o + i] = sb[oi + 2*i] + sb[oi + 2*i + 1];
        __syncthreads();
    }
}
__device__ __forceinline__ void upsweep(float* sb, int tid) {
    for (int l = 11; l >= 0; l--) {
        int sz = SS >> l;
        int o  = c_off[l], ou = c_off[l+1];
        for (int i = tid; i < sz; i += 512) {
            float v;
            if (i & 1)          v = sb[ou + (i >> 1)];
            else if (i == 0)    v = sb[o];
            else                v = sb[ou + (i >> 1) - 1] + sb[o + i];
            sb[o + i] = v;
        }
        __syncthreads();
    }
}

__global__ __launch_bounds__(512)
void scan_kernel(const int* __restrict__ tl, float* __restrict__ alpha_sum_out) {
    __shared__ float sb[8192];
    int b   = blockIdx.x;
    int tid = threadIdx.x;

    for (int s = tid; s < SS; s += 512) sb[s] = g_sig[b * SS + s];
    __syncthreads();

    downsweep(sb, tid);
    float asum = sb[c_off[12]];
    if (tid == 0) alpha_sum_out[b] = asum;
    float tlf = (float)tl[b];
    __syncthreads();

    for (int s = tid; s < SS; s += 512) {
        float sc = (sb[s] * tlf) / asum;
        sb[s] = sc;
        g_alpha[b * SS + s] = sc;
    }
    __syncthreads();

    downsweep(sb, tid);
    upsweep(sb, tid);

    for (int s = tid; s < SS; s += 512) {
        float c = sb[s];
        g_csum[b * SS + s] = c;
        g_f  [b * SS + s] = (int)floorf(c + 1e-4f);
    }

    // ---- build inverse map: inv[t] = first s with f[s] >= t ----
    for (int i = tid; i < INVN; i += 512)
        g_inv[b * INVN + i] = (i == 0) ? 0 : SS;
    __syncthreads();
    for (int s = tid; s < SS; s += 512) {
        int d1 = (int)floorf(sb[s] + 1e-4f);
        int d0 = (s == 0) ? 0 : (int)floorf(sb[s - 1] + 1e-4f);
        int te = d1 < (INVN - 1) ? d1 : (INVN - 1);
        for (int t = d0 + 1; t <= te; t++)
            g_inv[b * INVN + t] = s;     // disjoint ranges: no race
    }
}

// ---------------- Phase 2: gather, TT=4, per-thread cp.async ring -------------------
#define TT 4
#define NSLOT 4   // per-thread 4 x 16B ring slots

__global__ __launch_bounds__(256)
void gather_kernel(const float* __restrict__ x) {
    int blk = blockIdx.x;              // b * 128 + tg
    int b   = blk >> 7;
    int tg  = blk & 127;
    int t0  = tg * TT;
    const int*   f  = g_f     + b * SS;
    const float* al = g_alpha + b * SS;
    const float* cs = g_csum  + b * SS;
    const int*   iv = g_inv   + b * INVN;

    int lo  = (t0 == 0) ? 0 : iv[t0 - 1];
    int hiv = iv[t0 + TT];
    int hi  = (hiv < SS - 1) ? hiv : SS - 1;

    __shared__ float4 ring[NSLOT * 256];   // 16 KB; reused as reduction buffer
    __shared__ float4 wbuf[144];

    int tid  = threadIdx.x;
    int half = tid >> 7;
    int l128 = tid & 127;
    int c0   = l128 * 4;
    uint32_t ringb = sm32(ring) + (uint32_t)tid * 16;

    float4 acc[TT];
    #pragma unroll
    for (int tt = 0; tt < TT; tt++) acc[tt] = make_float4(0.f, 0.f, 0.f, 0.f);

    if (tid >= 128 && tid < 144) wbuf[tid] = make_float4(0.f, 0.f, 0.f, 0.f);

    for (int base = lo; base <= hi; base += 128) {
        asm volatile("cp.async.wait_group 0;" ::: "memory");
        if (tid < 128) {
            int s = base + tid;
            float4 wv = make_float4(0.f, 0.f, 0.f, 0.f);
            if (s <= hi) {
                int   d1   = f[s];
                int   d0   = (s == 0) ? 0 : f[s - 1];
                int   fire = d1 - d0;
                float a    = al[s];
                float c    = cs[s];
                float ex   = (fire > 1) ? (float)(fire - 1) : 0.f;
                float rw   = (fire > 0) ? (c - (float)d1) : a;
                float lw   = (a - rw) - ex;
                int   ei   = d0 + 1; if (ei > TMAX - 1) ei = TMAX - 1;
                float exc  = fminf(ex, 1.0f);
                float w[TT];
                #pragma unroll
                for (int tt = 0; tt < TT; tt++) {
                    int t = t0 + tt;
                    float ww = 0.f;
                    if (d1 == t) ww += rw;
                    if (d0 == t) ww += lw;
                    if (ei == t) ww += exc;
                    if (t >= d0 + 2 && t < d1) ww = 1.0f;
                    w[tt] = ww;
                }
                wv = make_float4(w[0], w[1], w[2], w[3]);
            }
            wbuf[tid] = wv;
        }
        __syncthreads();

        int n = hi - base + 1; if (n > 128) n = 128;
        const float* xp = x + (size_t)base * (BB*CC) + b * CC + c0;
        int ih = (n - half + 1) >> 1;

        #pragma unroll
        for (int i = 0; i < NSLOT; i++) {
            int r = 2*i + half; r = r < n ? r : n - 1;
            cpa16(ringb + (uint32_t)(i * 256) * 16, xp + (size_t)r * (BB*CC));
            asm volatile("cp.async.commit_group;" ::: "memory");
        }
        for (int i = 0; i < ih; i++) {
            asm volatile("cp.async.wait_group %0;" :: "n"(NSLOT - 1) : "memory");
            int slot = i & (NSLOT - 1);
            float4 v = ring[slot * 256 + tid];
            int r = 2*(i + NSLOT) + half; r = r < n ? r : n - 1;
            cpa16(ringb + (uint32_t)(slot * 256) * 16, xp + (size_t)r * (BB*CC));
            asm volatile("cp.async.commit_group;" ::: "memory");

            float4 wq = wbuf[2*i + half];
            acc[0].x += wq.x * v.x; acc[0].y += wq.x * v.y;
            acc[0].z += wq.x * v.z; acc[0].w += wq.x * v.w;
            acc[1].x += wq.y * v.x; acc[1].y += wq.y * v.y;
            acc[1].z += wq.y * v.z; acc[1].w += wq.y * v.w;
            acc[2].x += wq.z * v.x; acc[2].y += wq.z * v.y;
            acc[2].z += wq.z * v.z; acc[2].w += wq.z * v.w;
            acc[3].x += wq.w * v.x; acc[3].y += wq.w * v.y;
            acc[3].z += wq.w * v.z; acc[3].w += wq.w * v.w;
        }
        __syncthreads();
    }

    asm volatile("cp.async.wait_group 0;" ::: "memory");
    __syncthreads();
    if (half == 1) {
        #pragma unroll
        for (int tt = 0; tt < TT; tt++) ring[tt * 128 + l128] = acc[tt];
    }
    __syncthreads();
    if (half == 0) {
        #pragma unroll
        for (int tt = 0; tt < TT; tt++) {
            float4 o = ring[tt * 128 + l128];
            float4 a = acc[tt];
            a.x += o.x; a.y += o.y; a.z += o.z; a.w += o.w;
            if (l128 == 127) a.w = 0.f;
            __half h0 = __float2half(a.x), h1 = __float2half(a.y);
            __half h2 = __float2half(a.z), h3 = __float2half(a.w);
            __half l0 = __float2half(a.x - __half2float(h0));
            __half l1 = __float2half(a.y - __half2float(h1));
            __half l2 = __float2half(a.z - __half2float(h2));
            __half l3 = __float2half(a.w - __half2float(h3));
            uint2 uh, ul;
            uh.x = (uint32_t)__half_as_ushort(h0) | ((uint32_t)__half_as_ushort(h1) << 16);
            uh.y = (uint32_t)__half_as_ushort(h2) | ((uint32_t)__half_as_ushort(h3) << 16);
            ul.x = (uint32_t)__half_as_ushort(l0) | ((uint32_t)__half_as_ushort(l1) << 16);
            ul.y = (uint32_t)__half_as_ushort(l2) | ((uint32_t)__half_as_ushort(l3) << 16);
            size_t o2 = (size_t)(b * 512 + t0 + tt) * 512 + c0;
            *(uint2*)&g_Ah[o2] = uh;
            *(uint2*)&g_Al[o2] = ul;
        }
    }
}

// ---------------- Phase 3: fp16 2-product GEMM, 64x128 tiles, 3 CTAs/SM -------------
#define GBM 64
#define GBN 128
#define GBK 32
#define AST 40
#define A_ELEMS (64 * AST)                       // 2560 halfs per A buf
#define B_ELEMS (128 * AST)                      // 5120 halfs
#define STAGE_ELEMS (2 * A_ELEMS + B_ELEMS)      // 10240 halfs = 20480 B
#define SMEM_GEMM (3 * STAGE_ELEMS * 2)          // 61440 B

__device__ __forceinline__ void ldsm4(uint32_t* r, uint32_t addr) {
    asm volatile("ldmatrix.sync.aligned.m8n8.x4.shared.b16 {%0,%1,%2,%3}, [%4];"
        : "=r"(r[0]), "=r"(r[1]), "=r"(r[2]), "=r"(r[3]) : "r"(addr));
}
__device__ __forceinline__ void mma16816(float* c, const uint32_t* a, const uint32_t* b) {
    asm volatile("mma.sync.aligned.m16n8k16.row.col.f32.f16.f16.f32 "
        "{%0,%1,%2,%3}, {%4,%5,%6,%7}, {%8,%9}, {%0,%1,%2,%3};"
        : "+f"(c[0]), "+f"(c[1]), "+f"(c[2]), "+f"(c[3])
        : "r"(a[0]), "r"(a[1]), "r"(a[2]), "r"(a[3]), "r"(b[0]), "r"(b[1]));
}

extern __shared__ __align__(16) __half dsm[];

__global__ __launch_bounds__(256, 3)
void gemm_kernel(const float* __restrict__ bias, const int* __restrict__ tl,
                 float* __restrict__ out) {
    int tid  = threadIdx.x;
    int wid  = tid >> 5, lane = tid & 31;
    int wm   = wid & 1,  wn   = wid >> 1;       // warp grid 2 x 4, warp tile 32x32
    // n-major grid: 4 n-blocks of the same m launch adjacently -> A tile L2 reuse
    int bm   = blockIdx.y * GBM;
    int bn   = blockIdx.x * GBN;
    int lq   = lane >> 2;
    int lr   = lane & 3;

    // all-zero M-block skip: rows t > tl[b] have zero feats -> out = bias
    {
        int bb  = bm >> 9;
        int t0b = bm & 511;
        if (t0b > tl[bb]) {
            int rowi = tid >> 2;                 // 0..63
            int cq   = (tid & 3) * 32;           // col offset 0/32/64/96
            int t    = t0b + rowi;
            float* op = out + (size_t)t * (BB * CC) + bb * CC + bn + cq;
            const float* bp = bias + bn + cq;
            #pragma unroll
            for (int j = 0; j < 32; j += 4)
                *(float4*)(op + j) = *(const float4*)(bp + j);
            return;
        }
    }

    uint32_t smb = sm32(dsm);

    // copy mapping:
    //  A bufs: 64 rows x 4x16B pieces = 256 pieces -> 1/thread: row=tid>>2, off=(tid&3)*8
    //  B buf : 128 rows x 4x16B pieces = 512 pieces -> 2/thread:
    //          row=tid>>1, half-offs (tid&1)*16 and (tid&1)*16+8
    int ar  = tid >> 2;
    int ap  = (tid & 3) * 8;        // halfs
    int br  = tid >> 1;
    int bp  = (tid & 1) * 16;       // halfs

    int arow = (lane & 7) + ((lane >> 3) & 1) * 8;   // A: row within 16
    int akc  = (lane >> 4) * 8;                      // A: k offset 0/8
    int bnof = (lane >> 4) * 8 + (lane & 7);         // B: n within 16
    int bkc  = ((lane >> 3) & 1) * 8;                // B: k offset 0/8

    float acc[2][4][4];
    #pragma unroll
    for (int mi = 0; mi < 2; mi++)
        #pragma unroll
        for (int ni = 0; ni < 4; ni++)
            #pragma unroll
            for (int q = 0; q < 4; q++) acc[mi][ni][q] = 0.f;

    const __half* gA  = g_Ah + (size_t)(bm + ar) * 512 + ap;
    const __half* gAl = g_Al + (size_t)(bm + ar) * 512 + ap;
    const __half* gB  = g_Bh + (size_t)(bn + br) * 512 + bp;

    #define ISSUE_STAGE(c, st) do {                                                     \
        int k0 = (c) * GBK;                                                             \
        uint32_t sbase = smb + (uint32_t)((st) * STAGE_ELEMS) * 2;                      \
        cpa16(sbase + (uint32_t)(ar * AST + ap) * 2,               gA  + k0);            \
        cpa16(sbase + (uint32_t)(A_ELEMS + ar * AST + ap) * 2,     gAl + k0);            \
        cpa16(sbase + (uint32_t)(2*A_ELEMS + br * AST + bp) * 2,   gB  + k0);            \
        cpa16(sbase + (uint32_t)(2*A_ELEMS + br * AST + bp + 8)*2, gB  + k0 + 8);        \
    } while (0)

    ISSUE_STAGE(0, 0);
    asm volatile("cp.async.commit_group;" ::: "memory");
    ISSUE_STAGE(1, 1);
    asm volatile("cp.async.commit_group;" ::: "memory");

    for (int c = 0; c < 16; c++) {
        int st = c % 3;
        asm volatile("cp.async.wait_group 1;" ::: "memory");
        __syncthreads();

        uint32_t sbase = smb + (uint32_t)(st * STAGE_ELEMS) * 2;
        uint32_t sAh = sbase;
        uint32_t sAl = sbase + (uint32_t)A_ELEMS * 2;
        uint32_t sBh = sbase + (uint32_t)(2 * A_ELEMS) * 2;

        #pragma unroll
        for (int ks = 0; ks < 2; ks++) {
            int kb = ks * 16;
            uint32_t bh[4][2];
            #pragma unroll
            for (int nip = 0; nip < 2; nip++) {
                int ncol = wn * 32 + nip * 16 + bnof;
                uint32_t off = (uint32_t)(ncol * AST + kb + bkc) * 2;
                uint32_t r[4];
                ldsm4(r, sBh + off);
                bh[nip*2+0][0] = r[0]; bh[nip*2+0][1] = r[1];
                bh[nip*2+1][0] = r[2]; bh[nip*2+1][1] = r[3];
            }
            #pragma unroll
            for (int mi = 0; mi < 2; mi++) {
                int row = wm * 32 + mi * 16 + arow;
                uint32_t off = (uint32_t)(row * AST + kb + akc) * 2;
                uint32_t a[4];
                ldsm4(a, sAh + off);
                #pragma unroll
                for (int ni = 0; ni < 4; ni++) mma16816(acc[mi][ni], a, bh[ni]);
                ldsm4(a, sAl + off);
                #pragma unroll
                for (int ni = 0; ni < 4; ni++) mma16816(acc[mi][ni], a, bh[ni]);
            }
        }

        if (c + 2 < 16) ISSUE_STAGE(c + 2, (c + 2) % 3);
        asm volatile("cp.async.commit_group;" ::: "memory");
    }

    // epilogue: out layout (T, B, C): idx = t*(B*C) + b*C + n, with m = b*512 + t
    #pragma unroll
    for (int mi = 0; mi < 2; mi++) {
        int mrow = bm + wm * 32 + mi * 16 + lq;
        #pragma unroll
        for (int half = 0; half < 2; half++) {
            int m = mrow + half * 8;
            int b = m >> 9;
            int t = m & 511;
            float* op = out + (size_t)t * (BB * CC) + b * CC + bn;
            #pragma unroll
            for (int ni = 0; ni < 4; ni++) {
                int nloc = wn * 32 + ni * 8 + lr * 2;
                float2 v;
                v.x = acc[mi][ni][half * 2 + 0] + bias[bn + nloc];
                v.y = acc[mi][ni][half * 2 + 1] + bias[bn + nloc + 1];
                *(float2*)(op + nloc) = v;
            }
        }
    }
}

// ---------------- launch ------------------------------------------------------------
extern "C" void kernel_launch(void* const* d_in, const int* in_sizes, int n_in,
                              void* d_out, int out_size) {
    const float*         x    = (const float*)d_in[0];
    const unsigned char* mask = (const unsigned char*)d_in[1];
    const int*           tl   = (const int*)d_in[2];
    const float*         W    = (const float*)d_in[3];
    const float*         bias = (const float*)d_in[4];
    float*               out  = (float*)d_out;

    float* asum_out = out + (size_t)TMAX * BB * CC;

    cudaFuncSetAttribute(gemm_kernel, cudaFuncAttributeMaxDynamicSharedMemorySize, SMEM_GEMM);

    misc_kernel<<<256 + 1024, 256>>>(x, mask, W);
    scan_kernel<<<BB, 512>>>(tl, asum_out);
    gather_kernel<<<BB * 128, 256>>>(x);
    gemm_kernel<<<dim3(512 / GBN, 8192 / GBM), 256, SMEM_GEMM>>>(bias, tl, out);
}